// round 2
// baseline (speedup 1.0000x reference)
#include <cuda_runtime.h>
#include <math.h>
#include <float.h>

#define B_   4
#define CIN  256
#define CP   128
#define NS   4096

// ---- scratch (static device globals; no allocation allowed) ----
__device__ float g_t[B_*CP*NS];
__device__ float g_p[B_*CP*NS];
__device__ float g_g[B_*CP*NS];
__device__ float g_y[B_*CP*NS];
__device__ float g_z[B_*CIN*NS];
__device__ float g_s[(size_t)B_*NS*NS];        // attention logits s[b][m][n], 268 MB
__device__ float g_rowmax[B_*NS];
__device__ float g_rowsuminv[B_*NS];
__device__ float g_mean[CIN];
__device__ float g_invstd[CIN];

// ============================================================================
// Kernel 1: projections t/p/g = W @ x  (NN SGEMM, M=128, K=256, N=4096)
// grid (32, 3, 4): x=n-tile, y=which weight, z=batch
// ============================================================================
__global__ __launch_bounds__(256) void proj_kernel(
    const float* __restrict__ x,
    const float* __restrict__ Wt, const float* __restrict__ Wp,
    const float* __restrict__ Wg)
{
    const int b = blockIdx.z;
    const int w = blockIdx.y;
    const float* A = (w == 0) ? Wt : (w == 1) ? Wp : Wg;   // [CP, CIN] k-contig
    float* Cout = ((w == 0) ? g_t : (w == 1) ? g_p : g_g) + (size_t)b*CP*NS;
    const float* Bm = x + (size_t)b*CIN*NS;                 // [CIN, NS]
    const int n0 = blockIdx.x * 128;

    __shared__ float As[16][128];
    __shared__ float Bs[16][128];
    float acc[8][8] = {};

    const int tid  = threadIdx.x;
    const int trow = tid / 16, tcol = tid % 16;
    const int aRow = tid >> 2,  aCol = (tid & 3) * 4;
    const int bRow = tid >> 5,  bCol = (tid & 31) * 4;

    for (int k0 = 0; k0 < CIN; k0 += 16) {
        #pragma unroll
        for (int r = 0; r < 2; r++) {
            int row = aRow + r*64;
            float4 v = *(const float4*)(A + (size_t)row*CIN + k0 + aCol);
            As[aCol+0][row] = v.x; As[aCol+1][row] = v.y;
            As[aCol+2][row] = v.z; As[aCol+3][row] = v.w;
        }
        #pragma unroll
        for (int r = 0; r < 2; r++) {
            int krow = bRow + r*8;
            *(float4*)&Bs[krow][bCol] =
                *(const float4*)(Bm + (size_t)(k0+krow)*NS + n0 + bCol);
        }
        __syncthreads();
        #pragma unroll
        for (int kk = 0; kk < 16; kk++) {
            float a[8], bb[8];
            #pragma unroll
            for (int i = 0; i < 8; i++) a[i]  = As[kk][trow*8 + i];
            #pragma unroll
            for (int j = 0; j < 8; j++) bb[j] = Bs[kk][tcol*8 + j];
            #pragma unroll
            for (int i = 0; i < 8; i++)
                #pragma unroll
                for (int j = 0; j < 8; j++) acc[i][j] += a[i]*bb[j];
        }
        __syncthreads();
    }
    #pragma unroll
    for (int i = 0; i < 8; i++) {
        int row = trow*8 + i;
        #pragma unroll
        for (int j = 0; j < 8; j += 4) {
            float4 v = make_float4(acc[i][j], acc[i][j+1], acc[i][j+2], acc[i][j+3]);
            *(float4*)(Cout + (size_t)row*NS + n0 + tcol*8 + j) = v;
        }
    }
}

// ============================================================================
// Kernel 2: s[b][m][n] = sum_c p[b][c][m] * t[b][c][n]   (TN SGEMM, K=128)
// grid (32, 32, 4): x=n-tile, y=m-tile, z=batch
// ============================================================================
__global__ __launch_bounds__(256) void att_logits_kernel()
{
    const int b = blockIdx.z;
    const float* A  = g_p + (size_t)b*CP*NS;   // [K=CP][NS] m-contig
    const float* Bm = g_t + (size_t)b*CP*NS;   // [K=CP][NS] n-contig
    float* Cout = g_s + (size_t)b*NS*NS;
    const int m0 = blockIdx.y * 128;
    const int n0 = blockIdx.x * 128;

    __shared__ float As[16][128];
    __shared__ float Bs[16][128];
    float acc[8][8] = {};

    const int tid  = threadIdx.x;
    const int trow = tid / 16, tcol = tid % 16;
    const int bRow = tid >> 5, bCol = (tid & 31) * 4;

    for (int k0 = 0; k0 < CP; k0 += 16) {
        #pragma unroll
        for (int r = 0; r < 2; r++) {
            int krow = bRow + r*8;
            *(float4*)&As[krow][bCol] =
                *(const float4*)(A  + (size_t)(k0+krow)*NS + m0 + bCol);
            *(float4*)&Bs[krow][bCol] =
                *(const float4*)(Bm + (size_t)(k0+krow)*NS + n0 + bCol);
        }
        __syncthreads();
        #pragma unroll
        for (int kk = 0; kk < 16; kk++) {
            float a[8], bb[8];
            #pragma unroll
            for (int i = 0; i < 8; i++) a[i]  = As[kk][trow*8 + i];
            #pragma unroll
            for (int j = 0; j < 8; j++) bb[j] = Bs[kk][tcol*8 + j];
            #pragma unroll
            for (int i = 0; i < 8; i++)
                #pragma unroll
                for (int j = 0; j < 8; j++) acc[i][j] += a[i]*bb[j];
        }
        __syncthreads();
    }
    #pragma unroll
    for (int i = 0; i < 8; i++) {
        int row = m0 + trow*8 + i;
        #pragma unroll
        for (int j = 0; j < 8; j += 4) {
            float4 v = make_float4(acc[i][j], acc[i][j+1], acc[i][j+2], acc[i][j+3]);
            *(float4*)(Cout + (size_t)row*NS + n0 + tcol*8 + j) = v;
        }
    }
}

// ============================================================================
// Kernel 3: per-row (b,m) softmax stats over n:  max, 1/sum(exp)
// grid: B_*NS blocks, 256 threads
// ============================================================================
__global__ __launch_bounds__(256) void row_stats_kernel()
{
    const size_t row = blockIdx.x;
    const float* rp = g_s + row * NS;
    __shared__ float sh[NS];
    __shared__ float red[256];
    const int tid = threadIdx.x;

    float mx = -FLT_MAX;
    for (int i = tid; i < NS; i += 256) { float v = rp[i]; sh[i] = v; mx = fmaxf(mx, v); }
    red[tid] = mx; __syncthreads();
    #pragma unroll
    for (int s = 128; s > 0; s >>= 1) {
        if (tid < s) red[tid] = fmaxf(red[tid], red[tid + s]);
        __syncthreads();
    }
    const float m = red[0];
    __syncthreads();

    float ssum = 0.f;
    for (int i = tid; i < NS; i += 256) ssum += __expf(sh[i] - m);
    red[tid] = ssum; __syncthreads();
    #pragma unroll
    for (int s = 128; s > 0; s >>= 1) {
        if (tid < s) red[tid] += red[tid + s];
        __syncthreads();
    }
    if (tid == 0) { g_rowmax[row] = m; g_rowsuminv[row] = 1.0f / red[0]; }
}

// ============================================================================
// Kernel 4: y[b][c][n] = sum_m (g[b][c][m]/L[m]) * exp(s[b][m][n] - M[m])
// NN SGEMM with load-time transforms, M=128, K=4096, N=4096
// grid (32, 1, 4)
// ============================================================================
__global__ __launch_bounds__(256) void attn_apply_kernel()
{
    const int b = blockIdx.z;
    const float* A    = g_g + (size_t)b*CP*NS;   // [CP][K=NS] k-contig
    const float* Bm   = g_s + (size_t)b*NS*NS;   // [K=NS][NS]
    const float* rmax = g_rowmax    + (size_t)b*NS;
    const float* rinv = g_rowsuminv + (size_t)b*NS;
    float* Cout = g_y + (size_t)b*CP*NS;
    const int n0 = blockIdx.x * 128;

    __shared__ float As[16][128];
    __shared__ float Bs[16][128];
    float acc[8][8] = {};

    const int tid  = threadIdx.x;
    const int trow = tid / 16, tcol = tid % 16;
    const int aRow = tid >> 2,  aCol = (tid & 3) * 4;
    const int bRow = tid >> 5,  bCol = (tid & 31) * 4;

    for (int k0 = 0; k0 < NS; k0 += 16) {
        float4 rv = *(const float4*)(rinv + k0 + aCol);
        #pragma unroll
        for (int r = 0; r < 2; r++) {
            int row = aRow + r*64;
            float4 v = *(const float4*)(A + (size_t)row*NS + k0 + aCol);
            As[aCol+0][row] = v.x * rv.x; As[aCol+1][row] = v.y * rv.y;
            As[aCol+2][row] = v.z * rv.z; As[aCol+3][row] = v.w * rv.w;
        }
        #pragma unroll
        for (int r = 0; r < 2; r++) {
            int krow = bRow + r*8;
            int kg = k0 + krow;
            float mr = rmax[kg];
            float4 v = *(const float4*)(Bm + (size_t)kg*NS + n0 + bCol);
            Bs[krow][bCol+0] = __expf(v.x - mr);
            Bs[krow][bCol+1] = __expf(v.y - mr);
            Bs[krow][bCol+2] = __expf(v.z - mr);
            Bs[krow][bCol+3] = __expf(v.w - mr);
        }
        __syncthreads();
        #pragma unroll
        for (int kk = 0; kk < 16; kk++) {
            float a[8], bb[8];
            #pragma unroll
            for (int i = 0; i < 8; i++) a[i]  = As[kk][trow*8 + i];
            #pragma unroll
            for (int j = 0; j < 8; j++) bb[j] = Bs[kk][tcol*8 + j];
            #pragma unroll
            for (int i = 0; i < 8; i++)
                #pragma unroll
                for (int j = 0; j < 8; j++) acc[i][j] += a[i]*bb[j];
        }
        __syncthreads();
    }
    #pragma unroll
    for (int i = 0; i < 8; i++) {
        int row = trow*8 + i;
        #pragma unroll
        for (int j = 0; j < 8; j += 4) {
            float4 v = make_float4(acc[i][j], acc[i][j+1], acc[i][j+2], acc[i][j+3]);
            *(float4*)(Cout + (size_t)row*NS + n0 + tcol*8 + j) = v;
        }
    }
}

// ============================================================================
// Kernel 5: z = Wz @ y   (NN SGEMM, M=256, K=128, N=4096)
// grid (32, 2, 4)
// ============================================================================
__global__ __launch_bounds__(256) void z_gemm_kernel(const float* __restrict__ Wz)
{
    const int b = blockIdx.z;
    const float* Bm = g_y + (size_t)b*CP*NS;    // [CP][NS]
    float* Cout = g_z + (size_t)b*CIN*NS;
    const int m0 = blockIdx.y * 128;
    const int n0 = blockIdx.x * 128;

    __shared__ float As[16][128];
    __shared__ float Bs[16][128];
    float acc[8][8] = {};

    const int tid  = threadIdx.x;
    const int trow = tid / 16, tcol = tid % 16;
    const int aRow = tid >> 2,  aCol = (tid & 3) * 4;
    const int bRow = tid >> 5,  bCol = (tid & 31) * 4;

    for (int k0 = 0; k0 < CP; k0 += 16) {
        #pragma unroll
        for (int r = 0; r < 2; r++) {
            int row = aRow + r*64;
            float4 v = *(const float4*)(Wz + (size_t)(m0+row)*CP + k0 + aCol);
            As[aCol+0][row] = v.x; As[aCol+1][row] = v.y;
            As[aCol+2][row] = v.z; As[aCol+3][row] = v.w;
        }
        #pragma unroll
        for (int r = 0; r < 2; r++) {
            int krow = bRow + r*8;
            *(float4*)&Bs[krow][bCol] =
                *(const float4*)(Bm + (size_t)(k0+krow)*NS + n0 + bCol);
        }
        __syncthreads();
        #pragma unroll
        for (int kk = 0; kk < 16; kk++) {
            float a[8], bb[8];
            #pragma unroll
            for (int i = 0; i < 8; i++) a[i]  = As[kk][trow*8 + i];
            #pragma unroll
            for (int j = 0; j < 8; j++) bb[j] = Bs[kk][tcol*8 + j];
            #pragma unroll
            for (int i = 0; i < 8; i++)
                #pragma unroll
                for (int j = 0; j < 8; j++) acc[i][j] += a[i]*bb[j];
        }
        __syncthreads();
    }
    #pragma unroll
    for (int i = 0; i < 8; i++) {
        int row = m0 + trow*8 + i;
        #pragma unroll
        for (int j = 0; j < 8; j += 4) {
            float4 v = make_float4(acc[i][j], acc[i][j+1], acc[i][j+2], acc[i][j+3]);
            *(float4*)(Cout + (size_t)row*NS + n0 + tcol*8 + j) = v;
        }
    }
}

// ============================================================================
// Kernel 6: BatchNorm stats per channel over (B, N)
// grid: CIN blocks, 256 threads
// ============================================================================
__global__ __launch_bounds__(256) void bn_reduce_kernel()
{
    const int c = blockIdx.x;
    const int tid = threadIdx.x;
    float s = 0.f, s2 = 0.f;
    for (int b = 0; b < B_; b++) {
        const float* zp = g_z + ((size_t)b*CIN + c) * NS;
        for (int i = tid; i < NS; i += 256) { float v = zp[i]; s += v; s2 += v*v; }
    }
    __shared__ float r1[256], r2[256];
    r1[tid] = s; r2[tid] = s2; __syncthreads();
    #pragma unroll
    for (int st = 128; st > 0; st >>= 1) {
        if (tid < st) { r1[tid] += r1[tid+st]; r2[tid] += r2[tid+st]; }
        __syncthreads();
    }
    if (tid == 0) {
        const float inv_n = 1.0f / (float)(B_*NS);
        float mean = r1[0] * inv_n;
        float var  = r2[0] * inv_n - mean*mean;
        g_mean[c]   = mean;
        g_invstd[c] = rsqrtf(var + 1e-5f);
    }
}

// ============================================================================
// Kernel 7: out = (z - mean)*invstd*gamma + beta + x
// ============================================================================
__global__ __launch_bounds__(512) void bn_apply_kernel(
    const float* __restrict__ x, const float* __restrict__ gamma,
    const float* __restrict__ beta, float* __restrict__ out)
{
    size_t idx = (size_t)blockIdx.x * blockDim.x + threadIdx.x;
    if (idx >= (size_t)B_*CIN*NS) return;
    int c = (int)((idx / NS) % CIN);
    out[idx] = (g_z[idx] - g_mean[c]) * g_invstd[c] * gamma[c] + beta[c] + x[idx];
}

// ============================================================================
extern "C" void kernel_launch(void* const* d_in, const int* in_sizes, int n_in,
                              void* d_out, int out_size)
{
    const float* x     = (const float*)d_in[0];
    const float* Wt    = (const float*)d_in[1];
    const float* Wp    = (const float*)d_in[2];
    const float* Wg    = (const float*)d_in[3];
    const float* Wz    = (const float*)d_in[4];
    const float* gamma = (const float*)d_in[5];
    const float* beta  = (const float*)d_in[6];
    float* out = (float*)d_out;

    proj_kernel      <<<dim3(32, 3, 4),  256>>>(x, Wt, Wp, Wg);
    att_logits_kernel<<<dim3(32, 32, 4), 256>>>();
    row_stats_kernel <<<B_*NS,           256>>>();
    attn_apply_kernel<<<dim3(32, 1, 4),  256>>>();
    z_gemm_kernel    <<<dim3(32, 2, 4),  256>>>(Wz);
    bn_reduce_kernel <<<CIN,             256>>>();
    const int total = B_*CIN*NS;
    bn_apply_kernel  <<<(total + 511)/512, 512>>>(x, gamma, beta, out);
}

// round 4
// speedup vs baseline: 1.8801x; 1.8801x over previous
#include <cuda_runtime.h>
#include <cuda_bf16.h>
#include <math.h>
#include <stdint.h>

#define B_   4
#define CIN  256
#define CP   128
#define NS   4096

__device__ float g_t[B_*CP*NS];
__device__ float g_p[B_*CP*NS];
__device__ float g_g[B_*CP*NS];
__device__ float g_y[B_*CP*NS];
__device__ float g_z[B_*CIN*NS];
__device__ float g_E[(size_t)B_*NS*NS];   // exp(s)[b][m][n] fp32, 268MB
__device__ float g_Linv[B_*NS];
__device__ float g_mean[CIN];
__device__ float g_invstd[CIN];

// ---------------- helpers ----------------
__device__ __forceinline__ uint32_t smem_u32(const void* p) {
    uint32_t a;
    asm("{ .reg .u64 t; cvta.to.shared.u64 t, %1; cvt.u32.u64 %0, t; }" : "=r"(a) : "l"(p));
    return a;
}
__device__ __forceinline__ void ldm_x4_t(uint32_t* r, uint32_t addr) {
    asm volatile("ldmatrix.sync.aligned.m8n8.x4.trans.shared.b16 {%0,%1,%2,%3}, [%4];"
        : "=r"(r[0]), "=r"(r[1]), "=r"(r[2]), "=r"(r[3]) : "r"(addr));
}
__device__ __forceinline__ void ldm_x4(uint32_t* r, uint32_t addr) {
    asm volatile("ldmatrix.sync.aligned.m8n8.x4.shared.b16 {%0,%1,%2,%3}, [%4];"
        : "=r"(r[0]), "=r"(r[1]), "=r"(r[2]), "=r"(r[3]) : "r"(addr));
}
__device__ __forceinline__ void ldm_x2_t(uint32_t* r, uint32_t addr) {
    asm volatile("ldmatrix.sync.aligned.m8n8.x2.trans.shared.b16 {%0,%1}, [%2];"
        : "=r"(r[0]), "=r"(r[1]) : "r"(addr));
}
__device__ __forceinline__ void mma_bf16(float* c, const uint32_t* a, const uint32_t* b) {
    asm volatile("mma.sync.aligned.m16n8k16.row.col.f32.bf16.bf16.f32 "
        "{%0,%1,%2,%3}, {%4,%5,%6,%7}, {%8,%9}, {%0,%1,%2,%3};"
        : "+f"(c[0]), "+f"(c[1]), "+f"(c[2]), "+f"(c[3])
        : "r"(a[0]), "r"(a[1]), "r"(a[2]), "r"(a[3]), "r"(b[0]), "r"(b[1]));
}
__device__ __forceinline__ void split4(float4 v, uint2& h, uint2& l) {
    __nv_bfloat16 h0 = __float2bfloat16(v.x), h1 = __float2bfloat16(v.y);
    __nv_bfloat16 h2 = __float2bfloat16(v.z), h3 = __float2bfloat16(v.w);
    h.x = (uint32_t)__bfloat16_as_ushort(h0) | ((uint32_t)__bfloat16_as_ushort(h1) << 16);
    h.y = (uint32_t)__bfloat16_as_ushort(h2) | ((uint32_t)__bfloat16_as_ushort(h3) << 16);
    __nv_bfloat16 l0 = __float2bfloat16(v.x - __bfloat162float(h0));
    __nv_bfloat16 l1 = __float2bfloat16(v.y - __bfloat162float(h1));
    __nv_bfloat16 l2 = __float2bfloat16(v.z - __bfloat162float(h2));
    __nv_bfloat16 l3 = __float2bfloat16(v.w - __bfloat162float(h3));
    l.x = (uint32_t)__bfloat16_as_ushort(l0) | ((uint32_t)__bfloat16_as_ushort(l1) << 16);
    l.y = (uint32_t)__bfloat16_as_ushort(l2) | ((uint32_t)__bfloat16_as_ushort(l3) << 16);
}

// ============================================================
// fp32 SGEMM (proj + z)
// ============================================================
__global__ __launch_bounds__(256) void sgemm_nn(
    const float* __restrict__ A, const float* __restrict__ B, float* __restrict__ C,
    int K, size_t sBb, size_t sCb)
{
    const int b = blockIdx.z;
    const float* Bm = B + (size_t)b*sBb;
    float* Cout = C + (size_t)b*sCb;
    const int m0 = blockIdx.y*128, n0 = blockIdx.x*128;
    __shared__ float As[16][128], Bs[16][128];
    float acc[8][8] = {};
    const int tid = threadIdx.x, trow = tid/16, tcol = tid%16;
    const int aRow = tid>>2, aCol = (tid&3)*4, bRow = tid>>5, bCol = (tid&31)*4;
    for (int k0 = 0; k0 < K; k0 += 16) {
        #pragma unroll
        for (int r = 0; r < 2; r++) {
            int row = aRow + r*64;
            float4 v = *(const float4*)(A + (size_t)(m0+row)*K + k0 + aCol);
            As[aCol+0][row]=v.x; As[aCol+1][row]=v.y; As[aCol+2][row]=v.z; As[aCol+3][row]=v.w;
        }
        #pragma unroll
        for (int r = 0; r < 2; r++) {
            int kr = bRow + r*8;
            *(float4*)&Bs[kr][bCol] = *(const float4*)(Bm + (size_t)(k0+kr)*NS + n0 + bCol);
        }
        __syncthreads();
        #pragma unroll
        for (int kk = 0; kk < 16; kk++) {
            float a[8], bb[8];
            #pragma unroll
            for (int i = 0; i < 8; i++) a[i] = As[kk][trow*8+i];
            #pragma unroll
            for (int j = 0; j < 8; j++) bb[j] = Bs[kk][tcol*8+j];
            #pragma unroll
            for (int i = 0; i < 8; i++)
                #pragma unroll
                for (int j = 0; j < 8; j++) acc[i][j] += a[i]*bb[j];
        }
        __syncthreads();
    }
    #pragma unroll
    for (int i = 0; i < 8; i++) {
        int row = m0 + trow*8 + i;
        #pragma unroll
        for (int j = 0; j < 8; j += 4)
            *(float4*)(Cout + (size_t)row*NS + n0 + tcol*8 + j) =
                make_float4(acc[i][j],acc[i][j+1],acc[i][j+2],acc[i][j+3]);
    }
}

// ============================================================
// logits: s[m,n] = sum_c p[c,m] t[c,n]; E = exp(s) fp32 [m][n]; Linv
// grid (32 m-strips, B_), 256 thr, 8 warps (2m x 4n), HMMA 3-pass hi/lo
// smem tiles: [c=128 rows][128 cols] bf16, row stride 136
// ============================================================
#define LTS 136
#define LTB 34816u   // 128*136*2
#define L_SMEM (6u*LTB)   // Ah, Al, buf0{Bh,Bl}, buf1{Bh,Bl} = 208896

__global__ __launch_bounds__(256) void logits_mma()
{
    extern __shared__ char smem[];
    const int b = blockIdx.y, m0 = blockIdx.x*128;
    const int tid = threadIdx.x, wid = tid>>5, lane = tid&31;
    const uint32_t sb = smem_u32(smem);
    const float* psrc = g_p + (size_t)b*CP*NS + m0;
    const float* tsrc = g_t + (size_t)b*CP*NS;

    // stage A ([c][m] slice of p) hi/lo
    #pragma unroll
    for (int i = 0; i < 16; i++) {
        int idx = tid + i*256, row = idx>>5, c4 = (idx&31)*4;
        float4 v = *(const float4*)(psrc + (size_t)row*NS + c4);
        uint2 h, l; split4(v, h, l);
        uint32_t d = (uint32_t)(row*LTS + c4)*2;
        *(uint2*)(smem + d) = h;
        *(uint2*)(smem + LTB + d) = l;
    }
    // stage B chunk 0 -> buf0
    #pragma unroll
    for (int i = 0; i < 16; i++) {
        int idx = tid + i*256, row = idx>>5, c4 = (idx&31)*4;
        float4 v = *(const float4*)(tsrc + (size_t)row*NS + c4);
        uint2 h, l; split4(v, h, l);
        uint32_t d = (uint32_t)(row*LTS + c4)*2;
        *(uint2*)(smem + 2u*LTB + d) = h;
        *(uint2*)(smem + 3u*LTB + d) = l;
    }
    __syncthreads();

    const int mw = (wid&1)*64, nw = (wid>>1)*32;
    const uint32_t rowA = (lane&7) + ((lane>>4)<<3);
    const uint32_t colA = ((lane>>3)&1)*8;
    const uint32_t rowB = (lane&15);
    const int r0 = lane>>2, cb = (lane&3)*2;

    float acc[4][4][4] = {};
    float rs[4][2] = {};
    float4 stg[16];

    for (int nc = 0; nc < 32; nc++) {
        if (nc < 31) {
            const float* src = tsrc + (nc+1)*128;
            #pragma unroll
            for (int i = 0; i < 16; i++) {
                int idx = tid + i*256, row = idx>>5, c4 = (idx&31)*4;
                stg[i] = *(const float4*)(src + (size_t)row*NS + c4);
            }
        }
        const uint32_t bufB = sb + 2u*LTB + (uint32_t)(nc&1)*(2u*LTB);
        #pragma unroll
        for (int pass = 0; pass < 3; pass++) {
            const uint32_t aT = sb + (pass==2 ? LTB : 0u);
            const uint32_t bT = bufB + (pass==1 ? LTB : 0u);
            #pragma unroll
            for (int k0 = 0; k0 < 128; k0 += 16) {
                uint32_t a[4][4], bb[4][2];
                #pragma unroll
                for (int mt = 0; mt < 4; mt++)
                    ldm_x4_t(a[mt], aT + ((k0+rowA)*LTS + mw + mt*16 + colA)*2);
                #pragma unroll
                for (int nt = 0; nt < 4; nt++)
                    ldm_x2_t(bb[nt], bT + ((k0+rowB)*LTS + nw + nt*8)*2);
                #pragma unroll
                for (int mt = 0; mt < 4; mt++)
                    #pragma unroll
                    for (int nt = 0; nt < 4; nt++)
                        mma_bf16(acc[mt][nt], a[mt], bb[nt]);
            }
        }
        // epilogue: exp, rowsum, store E chunk
        #pragma unroll
        for (int mt = 0; mt < 4; mt++) {
            const int mg = m0 + mw + mt*16 + r0;
            #pragma unroll
            for (int nt = 0; nt < 4; nt++) {
                float e0 = __expf(acc[mt][nt][0]);
                float e1 = __expf(acc[mt][nt][1]);
                float e2 = __expf(acc[mt][nt][2]);
                float e3 = __expf(acc[mt][nt][3]);
                rs[mt][0] += e0 + e1;
                rs[mt][1] += e2 + e3;
                const int ng = nc*128 + nw + nt*8 + cb;
                *(float2*)(g_E + ((size_t)b*NS + mg)*NS + ng)     = make_float2(e0, e1);
                *(float2*)(g_E + ((size_t)b*NS + mg + 8)*NS + ng) = make_float2(e2, e3);
                acc[mt][nt][0] = acc[mt][nt][1] = acc[mt][nt][2] = acc[mt][nt][3] = 0.f;
            }
        }
        if (nc < 31) {
            const uint32_t nbuf = 2u*LTB + (uint32_t)((nc+1)&1)*(2u*LTB);
            #pragma unroll
            for (int i = 0; i < 16; i++) {
                int idx = tid + i*256, row = idx>>5, c4 = (idx&31)*4;
                uint2 h, l; split4(stg[i], h, l);
                uint32_t d = (uint32_t)(row*LTS + c4)*2;
                *(uint2*)(smem + nbuf + d) = h;
                *(uint2*)(smem + nbuf + LTB + d) = l;
            }
        }
        __syncthreads();
    }

    // rowsum reduce: 4-lane groups share rows
    #pragma unroll
    for (int mt = 0; mt < 4; mt++)
        #pragma unroll
        for (int h = 0; h < 2; h++) {
            rs[mt][h] += __shfl_xor_sync(0xFFFFFFFF, rs[mt][h], 1);
            rs[mt][h] += __shfl_xor_sync(0xFFFFFFFF, rs[mt][h], 2);
        }
    __syncthreads();
    float* red = (float*)smem;   // [4 nwarps][128 rows]
    if ((lane&3) == 0) {
        #pragma unroll
        for (int mt = 0; mt < 4; mt++)
            #pragma unroll
            for (int h = 0; h < 2; h++)
                red[(wid>>1)*128 + mw + mt*16 + r0 + h*8] = rs[mt][h];
    }
    __syncthreads();
    if (tid < 128)
        g_Linv[(size_t)b*NS + m0 + tid] =
            1.0f / (red[tid] + red[128+tid] + red[256+tid] + red[384+tid]);
}

// ============================================================
// gscale: g[b][c][m] *= Linv[b][m]  (in place)
// ============================================================
__global__ __launch_bounds__(256) void gscale_kernel()
{
    size_t idx = (size_t)blockIdx.x*256 + threadIdx.x;
    int m = (int)(idx % NS);
    int b = (int)(idx / ((size_t)CP*NS));
    g_g[idx] *= g_Linv[(size_t)b*NS + m];
}

// ============================================================
// apply: y[c,n] = sum_m g'[c,m] E[m,n]; K=4096 in 64-chunks, HMMA 3-pass
// grid (32 n-tiles, B_), 256 thr, 8 warps (2c x 4n)
// A smem [c=128][k=64] stride 72; B smem [k=64][n=128] stride 136
// ============================================================
#define ATS 72
#define ATB 18432u   // 128*72*2
#define BTS 136
#define BTB 17408u   // 64*136*2
#define ABUF (2u*ATB + 2u*BTB)   // 71680
#define T_SMEM (2u*ABUF)          // 143360

__global__ __launch_bounds__(256) void apply_mma()
{
    extern __shared__ char smem[];
    const int b = blockIdx.y, n0 = blockIdx.x*128;
    const int tid = threadIdx.x, wid = tid>>5, lane = tid&31;
    const uint32_t sb = smem_u32(smem);
    const float* Asrc = g_g + (size_t)b*CP*NS;
    const float* Bsrc = g_E + (size_t)b*NS*NS + n0;

    // stage chunk 0 -> buf0
    #pragma unroll
    for (int i = 0; i < 8; i++) {   // A: 128 rows x 16 uint4
        int idx = tid + i*256, row = idx>>4, c4 = (idx&15)*4;
        float4 v = *(const float4*)(Asrc + (size_t)row*NS + c4);
        uint2 h, l; split4(v, h, l);
        uint32_t d = (uint32_t)(row*ATS + c4)*2;
        *(uint2*)(smem + d) = h;
        *(uint2*)(smem + ATB + d) = l;
    }
    #pragma unroll
    for (int i = 0; i < 8; i++) {   // B: 64 rows x 32 uint4
        int idx = tid + i*256, row = idx>>5, c4 = (idx&31)*4;
        float4 v = *(const float4*)(Bsrc + (size_t)row*NS + c4);
        uint2 h, l; split4(v, h, l);
        uint32_t d = (uint32_t)(row*BTS + c4)*2;
        *(uint2*)(smem + 2u*ATB + d) = h;
        *(uint2*)(smem + 2u*ATB + BTB + d) = l;
    }
    __syncthreads();

    const int cw = (wid&1)*64, nw = (wid>>1)*32;
    const uint32_t rowAa = (lane&15);          // A non-trans
    const uint32_t colAa = (lane>>4)*8;
    const uint32_t rowB  = (lane&15);          // B trans
    const int r0 = lane>>2, cb = (lane&3)*2;

    float acc[4][4][4] = {};
    float4 stg[16];

    for (int kc = 0; kc < 64; kc++) {
        if (kc < 63) {
            const float* As2 = Asrc + (kc+1)*64;
            const float* Bs2 = Bsrc + (size_t)(kc+1)*64*NS;
            #pragma unroll
            for (int i = 0; i < 8; i++) {
                int idx = tid + i*256, row = idx>>4, c4 = (idx&15)*4;
                stg[i] = *(const float4*)(As2 + (size_t)row*NS + c4);
            }
            #pragma unroll
            for (int i = 0; i < 8; i++) {
                int idx = tid + i*256, row = idx>>5, c4 = (idx&31)*4;
                stg[8+i] = *(const float4*)(Bs2 + (size_t)row*NS + c4);
            }
        }
        const uint32_t buf = sb + (uint32_t)(kc&1)*ABUF;
        #pragma unroll
        for (int pass = 0; pass < 3; pass++) {
            const uint32_t aT = buf + (pass==2 ? ATB : 0u);
            const uint32_t bT = buf + 2u*ATB + (pass==1 ? BTB : 0u);
            #pragma unroll
            for (int k0 = 0; k0 < 64; k0 += 16) {
                uint32_t a[4][4], bb[4][2];
                #pragma unroll
                for (int ct = 0; ct < 4; ct++)
                    ldm_x4(a[ct], aT + ((cw + ct*16 + rowAa)*ATS + k0 + colAa)*2);
                #pragma unroll
                for (int nt = 0; nt < 4; nt++)
                    ldm_x2_t(bb[nt], bT + ((k0+rowB)*BTS + nw + nt*8)*2);
                #pragma unroll
                for (int ct = 0; ct < 4; ct++)
                    #pragma unroll
                    for (int nt = 0; nt < 4; nt++)
                        mma_bf16(acc[ct][nt], a[ct], bb[nt]);
            }
        }
        if (kc < 63) {
            const uint32_t nbuf = (uint32_t)((kc+1)&1)*ABUF;
            #pragma unroll
            for (int i = 0; i < 8; i++) {
                int idx = tid + i*256, row = idx>>4, c4 = (idx&15)*4;
                uint2 h, l; split4(stg[i], h, l);
                uint32_t d = (uint32_t)(row*ATS + c4)*2;
                *(uint2*)(smem + nbuf + d) = h;
                *(uint2*)(smem + nbuf + ATB + d) = l;
            }
            #pragma unroll
            for (int i = 0; i < 8; i++) {
                int idx = tid + i*256, row = idx>>5, c4 = (idx&31)*4;
                uint2 h, l; split4(stg[8+i], h, l);
                uint32_t d = (uint32_t)(row*BTS + c4)*2;
                *(uint2*)(smem + nbuf + 2u*ATB + d) = h;
                *(uint2*)(smem + nbuf + 2u*ATB + BTB + d) = l;
            }
        }
        __syncthreads();
    }

    #pragma unroll
    for (int ct = 0; ct < 4; ct++) {
        const int cg = cw + ct*16 + r0;
        #pragma unroll
        for (int nt = 0; nt < 4; nt++) {
            const int ng = n0 + nw + nt*8 + cb;
            *(float2*)(g_y + ((size_t)b*CP + cg)*NS + ng)     = make_float2(acc[ct][nt][0], acc[ct][nt][1]);
            *(float2*)(g_y + ((size_t)b*CP + cg + 8)*NS + ng) = make_float2(acc[ct][nt][2], acc[ct][nt][3]);
        }
    }
}

// ============================================================
// BatchNorm
// ============================================================
__global__ __launch_bounds__(256) void bn_reduce_kernel()
{
    const int c = blockIdx.x, tid = threadIdx.x;
    float s = 0.f, s2 = 0.f;
    for (int b = 0; b < B_; b++) {
        const float* zp = g_z + ((size_t)b*CIN + c)*NS;
        for (int i = tid; i < NS; i += 256) { float v = zp[i]; s += v; s2 += v*v; }
    }
    __shared__ float r1[256], r2[256];
    r1[tid] = s; r2[tid] = s2; __syncthreads();
    #pragma unroll
    for (int st = 128; st > 0; st >>= 1) {
        if (tid < st) { r1[tid] += r1[tid+st]; r2[tid] += r2[tid+st]; }
        __syncthreads();
    }
    if (tid == 0) {
        const float inv_n = 1.0f / (float)(B_*NS);
        float mean = r1[0]*inv_n, var = r2[0]*inv_n - mean*mean;
        g_mean[c] = mean;
        g_invstd[c] = rsqrtf(var + 1e-5f);
    }
}

__global__ __launch_bounds__(512) void bn_apply_kernel(
    const float* __restrict__ x, const float* __restrict__ gamma,
    const float* __restrict__ beta, float* __restrict__ out)
{
    size_t idx = (size_t)blockIdx.x*512 + threadIdx.x;
    int c = (int)((idx / NS) % CIN);
    out[idx] = (g_z[idx] - g_mean[c])*g_invstd[c]*gamma[c] + beta[c] + x[idx];
}

// ============================================================
extern "C" void kernel_launch(void* const* d_in, const int* in_sizes, int n_in,
                              void* d_out, int out_size)
{
    const float* x     = (const float*)d_in[0];
    const float* Wt    = (const float*)d_in[1];
    const float* Wp    = (const float*)d_in[2];
    const float* Wg    = (const float*)d_in[3];
    const float* Wz    = (const float*)d_in[4];
    const float* gamma = (const float*)d_in[5];
    const float* beta  = (const float*)d_in[6];
    float* out = (float*)d_out;

    cudaFuncSetAttribute(logits_mma, cudaFuncAttributeMaxDynamicSharedMemorySize, L_SMEM);
    cudaFuncSetAttribute(apply_mma,  cudaFuncAttributeMaxDynamicSharedMemorySize, T_SMEM);

    float* d_t; cudaGetSymbolAddress((void**)&d_t, g_t);
    float* d_p; cudaGetSymbolAddress((void**)&d_p, g_p);
    float* d_g; cudaGetSymbolAddress((void**)&d_g, g_g);
    float* d_y; cudaGetSymbolAddress((void**)&d_y, g_y);
    float* d_z; cudaGetSymbolAddress((void**)&d_z, g_z);

    sgemm_nn<<<dim3(32,1,4), 256>>>(Wt, x, d_t, CIN, (size_t)CIN*NS, (size_t)CP*NS);
    sgemm_nn<<<dim3(32,1,4), 256>>>(Wp, x, d_p, CIN, (size_t)CIN*NS, (size_t)CP*NS);
    sgemm_nn<<<dim3(32,1,4), 256>>>(Wg, x, d_g, CIN, (size_t)CIN*NS, (size_t)CP*NS);
    logits_mma<<<dim3(32,4), 256, L_SMEM>>>();
    gscale_kernel<<<(B_*CP*NS)/256, 256>>>();
    apply_mma<<<dim3(32,4), 256, T_SMEM>>>();
    sgemm_nn<<<dim3(32,2,4), 256>>>(Wz, d_y, d_z, CP, (size_t)CP*NS, (size_t)CIN*NS);
    bn_reduce_kernel<<<CIN, 256>>>();
    bn_apply_kernel<<<(B_*CIN*NS)/512, 512>>>(x, gamma, beta, out);
}

// round 5
// speedup vs baseline: 1.9772x; 1.0516x over previous
#include <cuda_runtime.h>
#include <cuda_bf16.h>
#include <math.h>
#include <stdint.h>

#define B_   4
#define CIN  256
#define CP   128
#define NS   4096

__device__ float g_g[B_*CP*NS];
__device__ float g_y[B_*CP*NS];
__device__ float g_z[B_*CIN*NS];
__device__ float g_Linv[B_*NS];
__device__ float g_mean[CIN];
__device__ float g_invstd[CIN];
__device__ __nv_bfloat16 g_th[B_*CP*NS], g_tl[B_*CP*NS];
__device__ __nv_bfloat16 g_ph[B_*CP*NS], g_pl[B_*CP*NS];
__device__ __nv_bfloat16 g_gh[B_*CP*NS], g_gl[B_*CP*NS];
__device__ __nv_bfloat16 g_Eh[(size_t)B_*NS*NS], g_El[(size_t)B_*NS*NS];

// ---------------- helpers ----------------
__device__ __forceinline__ uint32_t smem_u32(const void* p) {
    uint32_t a;
    asm("{ .reg .u64 t; cvta.to.shared.u64 t, %1; cvt.u32.u64 %0, t; }" : "=r"(a) : "l"(p));
    return a;
}
#define CP16(dst, src) asm volatile("cp.async.cg.shared.global [%0], [%1], 16;" :: "r"(dst), "l"(src))
#define CPCOMMIT() asm volatile("cp.async.commit_group;" ::: "memory")
#define CPWAIT0() asm volatile("cp.async.wait_group 0;" ::: "memory")
#define CPWAIT1() asm volatile("cp.async.wait_group 1;" ::: "memory")

__device__ __forceinline__ void ldm_x4_t(uint32_t* r, uint32_t addr) {
    asm volatile("ldmatrix.sync.aligned.m8n8.x4.trans.shared.b16 {%0,%1,%2,%3}, [%4];"
        : "=r"(r[0]), "=r"(r[1]), "=r"(r[2]), "=r"(r[3]) : "r"(addr));
}
__device__ __forceinline__ void ldm_x4(uint32_t* r, uint32_t addr) {
    asm volatile("ldmatrix.sync.aligned.m8n8.x4.shared.b16 {%0,%1,%2,%3}, [%4];"
        : "=r"(r[0]), "=r"(r[1]), "=r"(r[2]), "=r"(r[3]) : "r"(addr));
}
__device__ __forceinline__ void ldm_x2_t(uint32_t* r, uint32_t addr) {
    asm volatile("ldmatrix.sync.aligned.m8n8.x2.trans.shared.b16 {%0,%1}, [%2];"
        : "=r"(r[0]), "=r"(r[1]) : "r"(addr));
}
__device__ __forceinline__ void mma_bf16(float* c, const uint32_t* a, const uint32_t* b) {
    asm volatile("mma.sync.aligned.m16n8k16.row.col.f32.bf16.bf16.f32 "
        "{%0,%1,%2,%3}, {%4,%5,%6,%7}, {%8,%9}, {%0,%1,%2,%3};"
        : "+f"(c[0]), "+f"(c[1]), "+f"(c[2]), "+f"(c[3])
        : "r"(a[0]), "r"(a[1]), "r"(a[2]), "r"(a[3]), "r"(b[0]), "r"(b[1]));
}
__device__ __forceinline__ void split2(float a, float b, uint32_t& h, uint32_t& l) {
    __nv_bfloat16 ha = __float2bfloat16(a), hb = __float2bfloat16(b);
    h = (uint32_t)__bfloat16_as_ushort(ha) | ((uint32_t)__bfloat16_as_ushort(hb) << 16);
    __nv_bfloat16 la = __float2bfloat16(a - __bfloat162float(ha));
    __nv_bfloat16 lb = __float2bfloat16(b - __bfloat162float(hb));
    l = (uint32_t)__bfloat16_as_ushort(la) | ((uint32_t)__bfloat16_as_ushort(lb) << 16);
}

// ============================================================
// proj: t/p/g = W @ x; t,p written as bf16 hi/lo; g fp32.
// grid (32, 3, 4), 256 thr
// ============================================================
__global__ __launch_bounds__(256) void proj_kernel(
    const float* __restrict__ x, const float* __restrict__ Wt,
    const float* __restrict__ Wp, const float* __restrict__ Wg)
{
    const int b = blockIdx.z, w = blockIdx.y;
    const float* A = (w == 0) ? Wt : (w == 1) ? Wp : Wg;
    const float* Bm = x + (size_t)b*CIN*NS;
    const int n0 = blockIdx.x * 128;
    __shared__ float As[16][128], Bs[16][128];
    float acc[8][8] = {};
    const int tid = threadIdx.x, trow = tid/16, tcol = tid%16;
    const int aRow = tid>>2, aCol = (tid&3)*4, bRow = tid>>5, bCol = (tid&31)*4;
    for (int k0 = 0; k0 < CIN; k0 += 16) {
        #pragma unroll
        for (int r = 0; r < 2; r++) {
            int row = aRow + r*64;
            float4 v = *(const float4*)(A + (size_t)row*CIN + k0 + aCol);
            As[aCol+0][row]=v.x; As[aCol+1][row]=v.y; As[aCol+2][row]=v.z; As[aCol+3][row]=v.w;
        }
        #pragma unroll
        for (int r = 0; r < 2; r++) {
            int kr = bRow + r*8;
            *(float4*)&Bs[kr][bCol] = *(const float4*)(Bm + (size_t)(k0+kr)*NS + n0 + bCol);
        }
        __syncthreads();
        #pragma unroll
        for (int kk = 0; kk < 16; kk++) {
            float a[8], bb[8];
            #pragma unroll
            for (int i = 0; i < 8; i++) a[i] = As[kk][trow*8+i];
            #pragma unroll
            for (int j = 0; j < 8; j++) bb[j] = Bs[kk][tcol*8+j];
            #pragma unroll
            for (int i = 0; i < 8; i++)
                #pragma unroll
                for (int j = 0; j < 8; j++) acc[i][j] += a[i]*bb[j];
        }
        __syncthreads();
    }
    if (w < 2) {
        __nv_bfloat16* dh = ((w == 0) ? g_th : g_ph) + (size_t)b*CP*NS;
        __nv_bfloat16* dl = ((w == 0) ? g_tl : g_pl) + (size_t)b*CP*NS;
        #pragma unroll
        for (int i = 0; i < 8; i++) {
            size_t ro = (size_t)(trow*8+i)*NS + n0 + tcol*8;
            #pragma unroll
            for (int j = 0; j < 8; j += 2) {
                uint32_t h, l; split2(acc[i][j], acc[i][j+1], h, l);
                *(uint32_t*)(dh + ro + j) = h;
                *(uint32_t*)(dl + ro + j) = l;
            }
        }
    } else {
        float* Cout = g_g + (size_t)b*CP*NS;
        #pragma unroll
        for (int i = 0; i < 8; i++) {
            int row = trow*8 + i;
            #pragma unroll
            for (int j = 0; j < 8; j += 4)
                *(float4*)(Cout + (size_t)row*NS + n0 + tcol*8 + j) =
                    make_float4(acc[i][j],acc[i][j+1],acc[i][j+2],acc[i][j+3]);
        }
    }
}

// ============================================================
// logits: s = p^T t (3-pass bf16); E = exp(s) hi/lo bf16; Linv
// grid (32, 4), 512 thr (16 warps, 4m x 4n of 32x32)
// ============================================================
#define LTS 136
#define LTB 34816u
#define L_SMEM (6u*LTB)

__device__ __forceinline__ void stage_pt(uint32_t dbase, const __nv_bfloat16* sh,
                                         const __nv_bfloat16* sl, int col0, int tid) {
    #pragma unroll
    for (int i = 0; i < 4; i++) {
        int idx = tid + i*512, row = idx>>4, ch = idx&15;
        uint32_t d = (uint32_t)(row*(LTS*2) + ch*16);
        CP16(dbase + d,       sh + (size_t)row*NS + col0 + ch*8);
        CP16(dbase + LTB + d, sl + (size_t)row*NS + col0 + ch*8);
    }
}

__global__ __launch_bounds__(512) void logits_mma()
{
    extern __shared__ char smem[];
    const int b = blockIdx.y, m0 = blockIdx.x*128;
    const int tid = threadIdx.x, wid = tid>>5, lane = tid&31;
    const uint32_t sb = smem_u32(smem);
    const __nv_bfloat16* th = g_th + (size_t)b*CP*NS;
    const __nv_bfloat16* tl = g_tl + (size_t)b*CP*NS;

    stage_pt(sb, g_ph + (size_t)b*CP*NS, g_pl + (size_t)b*CP*NS, m0, tid);  // A
    stage_pt(sb + 2u*LTB, th, tl, 0, tid);                                   // B0
    CPCOMMIT();
    stage_pt(sb + 4u*LTB, th, tl, 128, tid);                                 // B1
    CPCOMMIT();

    const int mw = (wid&3)*32, nw = (wid>>2)*32;
    const uint32_t rowA = (lane&7) + ((lane>>4)<<3);
    const uint32_t colA = ((lane>>3)&1)*8;
    const uint32_t rowB = (lane&15);
    const int r0 = lane>>2, cb = (lane&3)*2;

    float acc[2][4][4] = {};
    float rs[2][2] = {};

    for (int nc = 0; nc < 32; nc++) {
        if (nc >= 30) { CPWAIT0(); } else { CPWAIT1(); }
        __syncthreads();
        const uint32_t bufB = sb + 2u*LTB + (uint32_t)(nc&1)*(2u*LTB);
        #pragma unroll
        for (int pass = 0; pass < 3; pass++) {
            const uint32_t aT = sb + (pass==2 ? LTB : 0u);
            const uint32_t bT = bufB + (pass==1 ? LTB : 0u);
            #pragma unroll
            for (int k0 = 0; k0 < 128; k0 += 16) {
                uint32_t a[2][4], bb[4][2];
                #pragma unroll
                for (int mt = 0; mt < 2; mt++)
                    ldm_x4_t(a[mt], aT + ((k0+rowA)*LTS + mw + mt*16 + colA)*2);
                #pragma unroll
                for (int nt = 0; nt < 4; nt++)
                    ldm_x2_t(bb[nt], bT + ((k0+rowB)*LTS + nw + nt*8)*2);
                #pragma unroll
                for (int mt = 0; mt < 2; mt++)
                    #pragma unroll
                    for (int nt = 0; nt < 4; nt++)
                        mma_bf16(acc[mt][nt], a[mt], bb[nt]);
            }
        }
        __syncthreads();
        if (nc + 2 < 32) {
            stage_pt(sb + 2u*LTB + (uint32_t)(nc&1)*(2u*LTB), th, tl, (nc+2)*128, tid);
            CPCOMMIT();
        }
        // epilogue: exp, rowsum, store E hi/lo
        #pragma unroll
        for (int mt = 0; mt < 2; mt++) {
            const int mg = m0 + mw + mt*16 + r0;
            #pragma unroll
            for (int nt = 0; nt < 4; nt++) {
                float e0 = __expf(acc[mt][nt][0]);
                float e1 = __expf(acc[mt][nt][1]);
                float e2 = __expf(acc[mt][nt][2]);
                float e3 = __expf(acc[mt][nt][3]);
                rs[mt][0] += e0 + e1;
                rs[mt][1] += e2 + e3;
                const int ng = nc*128 + nw + nt*8 + cb;
                uint32_t h, l;
                size_t o = ((size_t)b*NS + mg)*NS + ng;
                split2(e0, e1, h, l);
                *(uint32_t*)(g_Eh + o) = h; *(uint32_t*)(g_El + o) = l;
                o += (size_t)8*NS;
                split2(e2, e3, h, l);
                *(uint32_t*)(g_Eh + o) = h; *(uint32_t*)(g_El + o) = l;
                acc[mt][nt][0]=acc[mt][nt][1]=acc[mt][nt][2]=acc[mt][nt][3]=0.f;
            }
        }
    }

    #pragma unroll
    for (int mt = 0; mt < 2; mt++)
        #pragma unroll
        for (int h = 0; h < 2; h++) {
            rs[mt][h] += __shfl_xor_sync(0xFFFFFFFF, rs[mt][h], 1);
            rs[mt][h] += __shfl_xor_sync(0xFFFFFFFF, rs[mt][h], 2);
        }
    __syncthreads();
    float* red = (float*)smem;   // [4 n-groups][128]
    if ((lane&3) == 0) {
        #pragma unroll
        for (int mt = 0; mt < 2; mt++)
            #pragma unroll
            for (int h = 0; h < 2; h++)
                red[(wid>>2)*128 + mw + mt*16 + r0 + h*8] = rs[mt][h];
    }
    __syncthreads();
    if (tid < 128)
        g_Linv[(size_t)b*NS + m0 + tid] =
            1.0f / (red[tid] + red[128+tid] + red[256+tid] + red[384+tid]);
}

// ============================================================
// gscale: g' = g * Linv[m] -> bf16 hi/lo
// ============================================================
__global__ __launch_bounds__(256) void gscale_kernel()
{
    size_t idx = (size_t)blockIdx.x*256 + threadIdx.x;
    int m = (int)(idx % NS);
    int b = (int)(idx / ((size_t)CP*NS));
    float v = g_g[idx] * g_Linv[(size_t)b*NS + m];
    __nv_bfloat16 h = __float2bfloat16(v);
    g_gh[idx] = h;
    g_gl[idx] = __float2bfloat16(v - __bfloat162float(h));
}

// ============================================================
// apply: y[c,n] = sum_m g'[c,m] E[m,n]; K=4096 (64 chunks), 3-pass
// grid (32, 4), 512 thr (16 warps, 4c x 4n of 32x32)
// ============================================================
#define ATS 72
#define ATB 18432u
#define BTS 136
#define BTB 17408u
#define ABUF (2u*ATB + 2u*BTB)
#define T_SMEM (2u*ABUF)

__device__ __forceinline__ void stage_apply(uint32_t buf, const __nv_bfloat16* Ah,
    const __nv_bfloat16* Al, const __nv_bfloat16* Bh, const __nv_bfloat16* Bl,
    int kc, int n0, int tid)
{
    #pragma unroll
    for (int i = 0; i < 2; i++) {   // A: 128 rows x 8 chunks
        int idx = tid + i*512, row = idx>>3, ch = idx&7;
        uint32_t d = (uint32_t)(row*(ATS*2) + ch*16);
        CP16(buf + d,       Ah + (size_t)row*NS + kc*64 + ch*8);
        CP16(buf + ATB + d, Al + (size_t)row*NS + kc*64 + ch*8);
    }
    #pragma unroll
    for (int i = 0; i < 2; i++) {   // B: 64 rows x 16 chunks
        int idx = tid + i*512, row = idx>>4, ch = idx&15;
        uint32_t d = (uint32_t)(row*(BTS*2) + ch*16);
        CP16(buf + 2u*ATB + d,       Bh + (size_t)(kc*64+row)*NS + n0 + ch*8);
        CP16(buf + 2u*ATB + BTB + d, Bl + (size_t)(kc*64+row)*NS + n0 + ch*8);
    }
}

__global__ __launch_bounds__(512) void apply_mma()
{
    extern __shared__ char smem[];
    const int b = blockIdx.y, n0 = blockIdx.x*128;
    const int tid = threadIdx.x, wid = tid>>5, lane = tid&31;
    const uint32_t sb = smem_u32(smem);
    const __nv_bfloat16* Ah = g_gh + (size_t)b*CP*NS;
    const __nv_bfloat16* Al = g_gl + (size_t)b*CP*NS;
    const __nv_bfloat16* Bh = g_Eh + (size_t)b*NS*NS;
    const __nv_bfloat16* Bl = g_El + (size_t)b*NS*NS;

    stage_apply(sb,        Ah, Al, Bh, Bl, 0, n0, tid); CPCOMMIT();
    stage_apply(sb + ABUF, Ah, Al, Bh, Bl, 1, n0, tid); CPCOMMIT();

    const int wc = (wid&3)*32, wn = (wid>>2)*32;
    const uint32_t rowAa = (lane&15), colAa = (lane>>4)*8;
    const uint32_t rowB = (lane&15);
    const int r0 = lane>>2, cb = (lane&3)*2;

    float acc[2][4][4] = {};

    for (int kc = 0; kc < 64; kc++) {
        if (kc >= 62) { CPWAIT0(); } else { CPWAIT1(); }
        __syncthreads();
        const uint32_t buf = sb + (uint32_t)(kc&1)*ABUF;
        #pragma unroll
        for (int pass = 0; pass < 3; pass++) {
            const uint32_t aT = buf + (pass==2 ? ATB : 0u);
            const uint32_t bT = buf + 2u*ATB + (pass==1 ? BTB : 0u);
            #pragma unroll
            for (int k0 = 0; k0 < 64; k0 += 16) {
                uint32_t a[2][4], bb[4][2];
                #pragma unroll
                for (int ct = 0; ct < 2; ct++)
                    ldm_x4(a[ct], aT + ((wc + ct*16 + rowAa)*ATS + k0 + colAa)*2);
                #pragma unroll
                for (int nt = 0; nt < 4; nt++)
                    ldm_x2_t(bb[nt], bT + ((k0+rowB)*BTS + wn + nt*8)*2);
                #pragma unroll
                for (int ct = 0; ct < 2; ct++)
                    #pragma unroll
                    for (int nt = 0; nt < 4; nt++)
                        mma_bf16(acc[ct][nt], a[ct], bb[nt]);
            }
        }
        __syncthreads();
        if (kc + 2 < 64) {
            stage_apply(sb + (uint32_t)(kc&1)*ABUF, Ah, Al, Bh, Bl, kc+2, n0, tid);
            CPCOMMIT();
        }
    }

    #pragma unroll
    for (int ct = 0; ct < 2; ct++) {
        const int cg = wc + ct*16 + r0;
        #pragma unroll
        for (int nt = 0; nt < 4; nt++) {
            const int ng = n0 + wn + nt*8 + cb;
            *(float2*)(g_y + ((size_t)b*CP + cg)*NS + ng)     = make_float2(acc[ct][nt][0], acc[ct][nt][1]);
            *(float2*)(g_y + ((size_t)b*CP + cg + 8)*NS + ng) = make_float2(acc[ct][nt][2], acc[ct][nt][3]);
        }
    }
}

// ============================================================
// z = Wz @ y (fp32 SGEMM), BatchNorm
// ============================================================
__global__ __launch_bounds__(256) void z_gemm(const float* __restrict__ Wz)
{
    const int b = blockIdx.z;
    const float* Bm = g_y + (size_t)b*CP*NS;
    float* Cout = g_z + (size_t)b*CIN*NS;
    const int m0 = blockIdx.y*128, n0 = blockIdx.x*128;
    __shared__ float As[16][128], Bs[16][128];
    float acc[8][8] = {};
    const int tid = threadIdx.x, trow = tid/16, tcol = tid%16;
    const int aRow = tid>>2, aCol = (tid&3)*4, bRow = tid>>5, bCol = (tid&31)*4;
    for (int k0 = 0; k0 < CP; k0 += 16) {
        #pragma unroll
        for (int r = 0; r < 2; r++) {
            int row = aRow + r*64;
            float4 v = *(const float4*)(Wz + (size_t)(m0+row)*CP + k0 + aCol);
            As[aCol+0][row]=v.x; As[aCol+1][row]=v.y; As[aCol+2][row]=v.z; As[aCol+3][row]=v.w;
        }
        #pragma unroll
        for (int r = 0; r < 2; r++) {
            int kr = bRow + r*8;
            *(float4*)&Bs[kr][bCol] = *(const float4*)(Bm + (size_t)(k0+kr)*NS + n0 + bCol);
        }
        __syncthreads();
        #pragma unroll
        for (int kk = 0; kk < 16; kk++) {
            float a[8], bb[8];
            #pragma unroll
            for (int i = 0; i < 8; i++) a[i] = As[kk][trow*8+i];
            #pragma unroll
            for (int j = 0; j < 8; j++) bb[j] = Bs[kk][tcol*8+j];
            #pragma unroll
            for (int i = 0; i < 8; i++)
                #pragma unroll
                for (int j = 0; j < 8; j++) acc[i][j] += a[i]*bb[j];
        }
        __syncthreads();
    }
    #pragma unroll
    for (int i = 0; i < 8; i++) {
        int row = m0 + trow*8 + i;
        #pragma unroll
        for (int j = 0; j < 8; j += 4)
            *(float4*)(Cout + (size_t)row*NS + n0 + tcol*8 + j) =
                make_float4(acc[i][j],acc[i][j+1],acc[i][j+2],acc[i][j+3]);
    }
}

__global__ __launch_bounds__(256) void bn_reduce_kernel()
{
    const int c = blockIdx.x, tid = threadIdx.x;
    float s = 0.f, s2 = 0.f;
    for (int b = 0; b < B_; b++) {
        const float* zp = g_z + ((size_t)b*CIN + c)*NS;
        for (int i = tid; i < NS; i += 256) { float v = zp[i]; s += v; s2 += v*v; }
    }
    __shared__ float r1[256], r2[256];
    r1[tid] = s; r2[tid] = s2; __syncthreads();
    #pragma unroll
    for (int st = 128; st > 0; st >>= 1) {
        if (tid < st) { r1[tid] += r1[tid+st]; r2[tid] += r2[tid+st]; }
        __syncthreads();
    }
    if (tid == 0) {
        const float inv_n = 1.0f / (float)(B_*NS);
        float mean = r1[0]*inv_n, var = r2[0]*inv_n - mean*mean;
        g_mean[c] = mean;
        g_invstd[c] = rsqrtf(var + 1e-5f);
    }
}

__global__ __launch_bounds__(512) void bn_apply_kernel(
    const float* __restrict__ x, const float* __restrict__ gamma,
    const float* __restrict__ beta, float* __restrict__ out)
{
    size_t idx = (size_t)blockIdx.x*512 + threadIdx.x;
    int c = (int)((idx / NS) % CIN);
    out[idx] = (g_z[idx] - g_mean[c])*g_invstd[c]*gamma[c] + beta[c] + x[idx];
}

// ============================================================
extern "C" void kernel_launch(void* const* d_in, const int* in_sizes, int n_in,
                              void* d_out, int out_size)
{
    const float* x     = (const float*)d_in[0];
    const float* Wt    = (const float*)d_in[1];
    const float* Wp    = (const float*)d_in[2];
    const float* Wg    = (const float*)d_in[3];
    const float* Wz    = (const float*)d_in[4];
    const float* gamma = (const float*)d_in[5];
    const float* beta  = (const float*)d_in[6];
    float* out = (float*)d_out;

    cudaFuncSetAttribute(logits_mma, cudaFuncAttributeMaxDynamicSharedMemorySize, L_SMEM);
    cudaFuncSetAttribute(apply_mma,  cudaFuncAttributeMaxDynamicSharedMemorySize, T_SMEM);

    proj_kernel <<<dim3(32,3,4), 256>>>(x, Wt, Wp, Wg);
    logits_mma  <<<dim3(32,4), 512, L_SMEM>>>();
    gscale_kernel<<<(B_*CP*NS)/256, 256>>>();
    apply_mma   <<<dim3(32,4), 512, T_SMEM>>>();
    z_gemm      <<<dim3(32,2,4), 256>>>(Wz);
    bn_reduce_kernel<<<CIN, 256>>>();
    bn_apply_kernel<<<(B_*CIN*NS)/512, 512>>>(x, gamma, beta, out);
}

// round 6
// speedup vs baseline: 2.4872x; 1.2580x over previous
#include <cuda_runtime.h>
#include <cuda_bf16.h>
#include <math.h>
#include <stdint.h>

#define B_   4
#define CIN  256
#define CP   128
#define NS   4096

__device__ float g_g[B_*CP*NS];
__device__ float g_z[B_*CIN*NS];
__device__ float g_Linv[B_*NS];
__device__ float g_mean[CIN];
__device__ float g_invstd[CIN];
__device__ __nv_bfloat16 g_xh[B_*CIN*NS], g_xl[B_*CIN*NS];
__device__ __nv_bfloat16 g_Wth[CP*CIN], g_Wtl[CP*CIN];
__device__ __nv_bfloat16 g_Wph[CP*CIN], g_Wpl[CP*CIN];
__device__ __nv_bfloat16 g_Wgh[CP*CIN], g_Wgl[CP*CIN];
__device__ __nv_bfloat16 g_Wzh[CIN*CP], g_Wzl[CIN*CP];
__device__ __nv_bfloat16 g_th[B_*CP*NS], g_tl[B_*CP*NS];
__device__ __nv_bfloat16 g_ph[B_*CP*NS], g_pl[B_*CP*NS];
__device__ __nv_bfloat16 g_gh[B_*CP*NS], g_gl[B_*CP*NS];
__device__ __nv_bfloat16 g_yh[B_*CP*NS], g_yl[B_*CP*NS];
__device__ __nv_bfloat16 g_Eh[(size_t)B_*NS*NS], g_El[(size_t)B_*NS*NS];

// ---------------- helpers ----------------
__device__ __forceinline__ uint32_t smem_u32(const void* p) {
    uint32_t a;
    asm("{ .reg .u64 t; cvta.to.shared.u64 t, %1; cvt.u32.u64 %0, t; }" : "=r"(a) : "l"(p));
    return a;
}
#define CP16(dst, src) asm volatile("cp.async.cg.shared.global [%0], [%1], 16;" :: "r"(dst), "l"(src))
#define CPCOMMIT() asm volatile("cp.async.commit_group;" ::: "memory")
#define CPWAIT0() asm volatile("cp.async.wait_group 0;" ::: "memory")
#define CPWAIT1() asm volatile("cp.async.wait_group 1;" ::: "memory")

__device__ __forceinline__ void ldm_x4_t(uint32_t* r, uint32_t addr) {
    asm volatile("ldmatrix.sync.aligned.m8n8.x4.trans.shared.b16 {%0,%1,%2,%3}, [%4];"
        : "=r"(r[0]), "=r"(r[1]), "=r"(r[2]), "=r"(r[3]) : "r"(addr));
}
__device__ __forceinline__ void ldm_x4(uint32_t* r, uint32_t addr) {
    asm volatile("ldmatrix.sync.aligned.m8n8.x4.shared.b16 {%0,%1,%2,%3}, [%4];"
        : "=r"(r[0]), "=r"(r[1]), "=r"(r[2]), "=r"(r[3]) : "r"(addr));
}
__device__ __forceinline__ void ldm_x2_t(uint32_t* r, uint32_t addr) {
    asm volatile("ldmatrix.sync.aligned.m8n8.x2.trans.shared.b16 {%0,%1}, [%2];"
        : "=r"(r[0]), "=r"(r[1]) : "r"(addr));
}
__device__ __forceinline__ void mma_bf16(float* c, const uint32_t* a, const uint32_t* b) {
    asm volatile("mma.sync.aligned.m16n8k16.row.col.f32.bf16.bf16.f32 "
        "{%0,%1,%2,%3}, {%4,%5,%6,%7}, {%8,%9}, {%0,%1,%2,%3};"
        : "+f"(c[0]), "+f"(c[1]), "+f"(c[2]), "+f"(c[3])
        : "r"(a[0]), "r"(a[1]), "r"(a[2]), "r"(a[3]), "r"(b[0]), "r"(b[1]));
}
__device__ __forceinline__ void split2(float a, float b, uint32_t& h, uint32_t& l) {
    __nv_bfloat16 ha = __float2bfloat16(a), hb = __float2bfloat16(b);
    h = (uint32_t)__bfloat16_as_ushort(ha) | ((uint32_t)__bfloat16_as_ushort(hb) << 16);
    __nv_bfloat16 la = __float2bfloat16(a - __bfloat162float(ha));
    __nv_bfloat16 lb = __float2bfloat16(b - __bfloat162float(hb));
    l = (uint32_t)__bfloat16_as_ushort(la) | ((uint32_t)__bfloat16_as_ushort(lb) << 16);
}

// ============================================================
// elementwise fp32 -> bf16 hi/lo split
// ============================================================
__global__ __launch_bounds__(256) void split_kernel(
    const float* __restrict__ src, __nv_bfloat16* __restrict__ h,
    __nv_bfloat16* __restrict__ l, int n)
{
    int i = blockIdx.x*256 + threadIdx.x;
    if (i >= n) return;
    float v = src[i];
    __nv_bfloat16 hb = __float2bfloat16(v);
    h[i] = hb;
    l[i] = __float2bfloat16(v - __bfloat162float(hb));
}

// ============================================================
// generic 3-pass hi/lo bf16 HMMA GEMM:
//   C[b][m0..+128][n0..+128] = sum_k A[m,k] B[b][k,n]
// A: [M x K] k-contig hi/lo (batch stride sAb); B: [K x NS] n-contig hi/lo
// mode 0: fp32 C; mode 1: bf16 hi/lo Ch/Cl
// grid (NS/128, M/128, B_), 512 thr, warps 4c x 4n of 32x32
// ============================================================
#define ATS 72
#define ATB 18432u
#define BTS 136
#define BTB 17408u
#define ABUF (2u*ATB + 2u*BTB)
#define G_SMEM (2u*ABUF)

__device__ __forceinline__ void stage_g(uint32_t buf,
    const __nv_bfloat16* Ah, const __nv_bfloat16* Al,
    const __nv_bfloat16* Bh, const __nv_bfloat16* Bl,
    int kc, int m0, int n0, int K, int tid)
{
    #pragma unroll
    for (int i = 0; i < 2; i++) {   // A: 128 rows x 8 16B-chunks
        int idx = tid + i*512, row = idx>>3, ch = idx&7;
        uint32_t d = (uint32_t)(row*(ATS*2) + ch*16);
        size_t so = (size_t)(m0+row)*K + kc*64 + ch*8;
        CP16(buf + d,       Ah + so);
        CP16(buf + ATB + d, Al + so);
    }
    #pragma unroll
    for (int i = 0; i < 2; i++) {   // B: 64 rows x 16 chunks
        int idx = tid + i*512, row = idx>>4, ch = idx&15;
        uint32_t d = (uint32_t)(row*(BTS*2) + ch*16);
        size_t so = (size_t)(kc*64+row)*NS + n0 + ch*8;
        CP16(buf + 2u*ATB + d,       Bh + so);
        CP16(buf + 2u*ATB + BTB + d, Bl + so);
    }
}

__global__ __launch_bounds__(512) void hgemm3p(
    const __nv_bfloat16* __restrict__ Ah, const __nv_bfloat16* __restrict__ Al, size_t sAb,
    const __nv_bfloat16* __restrict__ Bh, const __nv_bfloat16* __restrict__ Bl, size_t sBb,
    float* __restrict__ C, __nv_bfloat16* __restrict__ Ch, __nv_bfloat16* __restrict__ Cl,
    size_t sCb, int K, int mode)
{
    extern __shared__ char smem[];
    const int b = blockIdx.z, m0 = blockIdx.y*128, n0 = blockIdx.x*128;
    const int tid = threadIdx.x, wid = tid>>5, lane = tid&31;
    const uint32_t sb = smem_u32(smem);
    const __nv_bfloat16* pAh = Ah + (size_t)b*sAb;
    const __nv_bfloat16* pAl = Al + (size_t)b*sAb;
    const __nv_bfloat16* pBh = Bh + (size_t)b*sBb;
    const __nv_bfloat16* pBl = Bl + (size_t)b*sBb;
    const int nk = K >> 6;

    stage_g(sb,        pAh, pAl, pBh, pBl, 0, m0, n0, K, tid); CPCOMMIT();
    stage_g(sb + ABUF, pAh, pAl, pBh, pBl, 1, m0, n0, K, tid); CPCOMMIT();

    const int wc = (wid&3)*32, wn = (wid>>2)*32;
    const uint32_t rowAa = (lane&15), colAa = (lane>>4)*8;
    const uint32_t rowB = (lane&15);
    const int r0 = lane>>2, cb = (lane&3)*2;

    float acc[2][4][4] = {};

    for (int kc = 0; kc < nk; kc++) {
        if (kc >= nk-2) { CPWAIT0(); } else { CPWAIT1(); }
        __syncthreads();
        const uint32_t buf = sb + (uint32_t)(kc&1)*ABUF;
        #pragma unroll
        for (int k0 = 0; k0 < 64; k0 += 16) {
            uint32_t ah[2][4], al[2][4], bh[4][2], bl[4][2];
            #pragma unroll
            for (int ct = 0; ct < 2; ct++) {
                uint32_t ao = buf + ((wc + ct*16 + rowAa)*ATS + k0 + colAa)*2;
                ldm_x4(ah[ct], ao);
                ldm_x4(al[ct], ao + ATB);
            }
            #pragma unroll
            for (int nt = 0; nt < 4; nt++) {
                uint32_t bo = buf + 2u*ATB + ((k0+rowB)*BTS + wn + nt*8)*2;
                ldm_x2_t(bh[nt], bo);
                ldm_x2_t(bl[nt], bo + BTB);
            }
            #pragma unroll
            for (int ct = 0; ct < 2; ct++)
                #pragma unroll
                for (int nt = 0; nt < 4; nt++) {
                    mma_bf16(acc[ct][nt], ah[ct], bh[nt]);
                    mma_bf16(acc[ct][nt], ah[ct], bl[nt]);
                    mma_bf16(acc[ct][nt], al[ct], bh[nt]);
                }
        }
        __syncthreads();
        if (kc + 2 < nk) {
            stage_g(sb + (uint32_t)(kc&1)*ABUF, pAh, pAl, pBh, pBl, kc+2, m0, n0, K, tid);
            CPCOMMIT();
        }
    }

    if (mode == 0) {
        float* Cout = C + (size_t)b*sCb;
        #pragma unroll
        for (int ct = 0; ct < 2; ct++) {
            const int cg = m0 + wc + ct*16 + r0;
            #pragma unroll
            for (int nt = 0; nt < 4; nt++) {
                const int ng = n0 + wn + nt*8 + cb;
                *(float2*)(Cout + (size_t)cg*NS + ng)     = make_float2(acc[ct][nt][0], acc[ct][nt][1]);
                *(float2*)(Cout + (size_t)(cg+8)*NS + ng) = make_float2(acc[ct][nt][2], acc[ct][nt][3]);
            }
        }
    } else {
        __nv_bfloat16* ch = Ch + (size_t)b*sCb;
        __nv_bfloat16* cl = Cl + (size_t)b*sCb;
        #pragma unroll
        for (int ct = 0; ct < 2; ct++) {
            const int cg = m0 + wc + ct*16 + r0;
            #pragma unroll
            for (int nt = 0; nt < 4; nt++) {
                const int ng = n0 + wn + nt*8 + cb;
                uint32_t h, l;
                split2(acc[ct][nt][0], acc[ct][nt][1], h, l);
                *(uint32_t*)(ch + (size_t)cg*NS + ng) = h;
                *(uint32_t*)(cl + (size_t)cg*NS + ng) = l;
                split2(acc[ct][nt][2], acc[ct][nt][3], h, l);
                *(uint32_t*)(ch + (size_t)(cg+8)*NS + ng) = h;
                *(uint32_t*)(cl + (size_t)(cg+8)*NS + ng) = l;
            }
        }
    }
}

// ============================================================
// logits: s = p^T t (3-pass fused); E = exp(s) hi/lo bf16; Linv
// grid (32, 4), 512 thr (16 warps, 4m x 4n of 32x32)
// ============================================================
#define LTS 136
#define LTB 34816u
#define L_SMEM (6u*LTB)

__device__ __forceinline__ void stage_pt(uint32_t dbase, const __nv_bfloat16* sh,
                                         const __nv_bfloat16* sl, int col0, int tid) {
    #pragma unroll
    for (int i = 0; i < 4; i++) {
        int idx = tid + i*512, row = idx>>4, ch = idx&15;
        uint32_t d = (uint32_t)(row*(LTS*2) + ch*16);
        CP16(dbase + d,       sh + (size_t)row*NS + col0 + ch*8);
        CP16(dbase + LTB + d, sl + (size_t)row*NS + col0 + ch*8);
    }
}

__global__ __launch_bounds__(512) void logits_mma()
{
    extern __shared__ char smem[];
    const int b = blockIdx.y, m0 = blockIdx.x*128;
    const int tid = threadIdx.x, wid = tid>>5, lane = tid&31;
    const uint32_t sb = smem_u32(smem);
    const __nv_bfloat16* th = g_th + (size_t)b*CP*NS;
    const __nv_bfloat16* tl = g_tl + (size_t)b*CP*NS;

    stage_pt(sb, g_ph + (size_t)b*CP*NS, g_pl + (size_t)b*CP*NS, m0, tid);  // A
    stage_pt(sb + 2u*LTB, th, tl, 0, tid);     CPCOMMIT();
    stage_pt(sb + 4u*LTB, th, tl, 128, tid);   CPCOMMIT();

    const int mw = (wid&3)*32, nw = (wid>>2)*32;
    const uint32_t rowA = (lane&7) + ((lane>>4)<<3);
    const uint32_t colA = ((lane>>3)&1)*8;
    const uint32_t rowB = (lane&15);
    const int r0 = lane>>2, cb = (lane&3)*2;

    float acc[2][4][4] = {};
    float rs[2][2] = {};

    for (int nc = 0; nc < 32; nc++) {
        if (nc >= 30) { CPWAIT0(); } else { CPWAIT1(); }
        __syncthreads();
        const uint32_t bufB = sb + 2u*LTB + (uint32_t)(nc&1)*(2u*LTB);
        #pragma unroll
        for (int k0 = 0; k0 < 128; k0 += 16) {
            uint32_t ah[2][4], al[2][4], bh[4][2], bl[4][2];
            #pragma unroll
            for (int mt = 0; mt < 2; mt++) {
                uint32_t ao = sb + ((k0+rowA)*LTS + mw + mt*16 + colA)*2;
                ldm_x4_t(ah[mt], ao);
                ldm_x4_t(al[mt], ao + LTB);
            }
            #pragma unroll
            for (int nt = 0; nt < 4; nt++) {
                uint32_t bo = bufB + ((k0+rowB)*LTS + nw + nt*8)*2;
                ldm_x2_t(bh[nt], bo);
                ldm_x2_t(bl[nt], bo + LTB);
            }
            #pragma unroll
            for (int mt = 0; mt < 2; mt++)
                #pragma unroll
                for (int nt = 0; nt < 4; nt++) {
                    mma_bf16(acc[mt][nt], ah[mt], bh[nt]);
                    mma_bf16(acc[mt][nt], ah[mt], bl[nt]);
                    mma_bf16(acc[mt][nt], al[mt], bh[nt]);
                }
        }
        __syncthreads();
        if (nc + 2 < 32) {
            stage_pt(sb + 2u*LTB + (uint32_t)(nc&1)*(2u*LTB), th, tl, (nc+2)*128, tid);
            CPCOMMIT();
        }
        // epilogue: exp, rowsum, store E hi/lo
        #pragma unroll
        for (int mt = 0; mt < 2; mt++) {
            const int mg = m0 + mw + mt*16 + r0;
            #pragma unroll
            for (int nt = 0; nt < 4; nt++) {
                float e0 = __expf(acc[mt][nt][0]);
                float e1 = __expf(acc[mt][nt][1]);
                float e2 = __expf(acc[mt][nt][2]);
                float e3 = __expf(acc[mt][nt][3]);
                rs[mt][0] += e0 + e1;
                rs[mt][1] += e2 + e3;
                const int ng = nc*128 + nw + nt*8 + cb;
                uint32_t h, l;
                size_t o = ((size_t)b*NS + mg)*NS + ng;
                split2(e0, e1, h, l);
                *(uint32_t*)(g_Eh + o) = h; *(uint32_t*)(g_El + o) = l;
                o += (size_t)8*NS;
                split2(e2, e3, h, l);
                *(uint32_t*)(g_Eh + o) = h; *(uint32_t*)(g_El + o) = l;
                acc[mt][nt][0]=acc[mt][nt][1]=acc[mt][nt][2]=acc[mt][nt][3]=0.f;
            }
        }
    }

    #pragma unroll
    for (int mt = 0; mt < 2; mt++)
        #pragma unroll
        for (int h = 0; h < 2; h++) {
            rs[mt][h] += __shfl_xor_sync(0xFFFFFFFF, rs[mt][h], 1);
            rs[mt][h] += __shfl_xor_sync(0xFFFFFFFF, rs[mt][h], 2);
        }
    __syncthreads();
    float* red = (float*)smem;
    if ((lane&3) == 0) {
        #pragma unroll
        for (int mt = 0; mt < 2; mt++)
            #pragma unroll
            for (int h = 0; h < 2; h++)
                red[(wid>>2)*128 + mw + mt*16 + r0 + h*8] = rs[mt][h];
    }
    __syncthreads();
    if (tid < 128)
        g_Linv[(size_t)b*NS + m0 + tid] =
            1.0f / (red[tid] + red[128+tid] + red[256+tid] + red[384+tid]);
}

// ============================================================
// gscale: g' = g * Linv[m] -> bf16 hi/lo
// ============================================================
__global__ __launch_bounds__(256) void gscale_kernel()
{
    size_t idx = (size_t)blockIdx.x*256 + threadIdx.x;
    int m = (int)(idx % NS);
    int b = (int)(idx / ((size_t)CP*NS));
    float v = g_g[idx] * g_Linv[(size_t)b*NS + m];
    __nv_bfloat16 h = __float2bfloat16(v);
    g_gh[idx] = h;
    g_gl[idx] = __float2bfloat16(v - __bfloat162float(h));
}

// ============================================================
// BatchNorm
// ============================================================
__global__ __launch_bounds__(256) void bn_reduce_kernel()
{
    const int c = blockIdx.x, tid = threadIdx.x;
    float s = 0.f, s2 = 0.f;
    for (int b = 0; b < B_; b++) {
        const float* zp = g_z + ((size_t)b*CIN + c)*NS;
        for (int i = tid; i < NS; i += 256) { float v = zp[i]; s += v; s2 += v*v; }
    }
    __shared__ float r1[256], r2[256];
    r1[tid] = s; r2[tid] = s2; __syncthreads();
    #pragma unroll
    for (int st = 128; st > 0; st >>= 1) {
        if (tid < st) { r1[tid] += r1[tid+st]; r2[tid] += r2[tid+st]; }
        __syncthreads();
    }
    if (tid == 0) {
        const float inv_n = 1.0f / (float)(B_*NS);
        float mean = r1[0]*inv_n, var = r2[0]*inv_n - mean*mean;
        g_mean[c] = mean;
        g_invstd[c] = rsqrtf(var + 1e-5f);
    }
}

__global__ __launch_bounds__(512) void bn_apply_kernel(
    const float* __restrict__ x, const float* __restrict__ gamma,
    const float* __restrict__ beta, float* __restrict__ out)
{
    size_t idx = (size_t)blockIdx.x*512 + threadIdx.x;
    int c = (int)((idx / NS) % CIN);
    out[idx] = (g_z[idx] - g_mean[c])*g_invstd[c]*gamma[c] + beta[c] + x[idx];
}

// ============================================================
extern "C" void kernel_launch(void* const* d_in, const int* in_sizes, int n_in,
                              void* d_out, int out_size)
{
    const float* x     = (const float*)d_in[0];
    const float* Wt    = (const float*)d_in[1];
    const float* Wp    = (const float*)d_in[2];
    const float* Wg    = (const float*)d_in[3];
    const float* Wz    = (const float*)d_in[4];
    const float* gamma = (const float*)d_in[5];
    const float* beta  = (const float*)d_in[6];
    float* out = (float*)d_out;

    cudaFuncSetAttribute(hgemm3p,   cudaFuncAttributeMaxDynamicSharedMemorySize, G_SMEM);
    cudaFuncSetAttribute(logits_mma, cudaFuncAttributeMaxDynamicSharedMemorySize, L_SMEM);

    __nv_bfloat16 *xh, *xl, *Wth, *Wtl, *Wph, *Wpl, *Wgh, *Wgl, *Wzh, *Wzl;
    __nv_bfloat16 *th, *tl, *ph, *pl, *gh, *gl, *yh, *yl, *Eh, *El;
    float *g, *z;
    cudaGetSymbolAddress((void**)&xh, g_xh);   cudaGetSymbolAddress((void**)&xl, g_xl);
    cudaGetSymbolAddress((void**)&Wth, g_Wth); cudaGetSymbolAddress((void**)&Wtl, g_Wtl);
    cudaGetSymbolAddress((void**)&Wph, g_Wph); cudaGetSymbolAddress((void**)&Wpl, g_Wpl);
    cudaGetSymbolAddress((void**)&Wgh, g_Wgh); cudaGetSymbolAddress((void**)&Wgl, g_Wgl);
    cudaGetSymbolAddress((void**)&Wzh, g_Wzh); cudaGetSymbolAddress((void**)&Wzl, g_Wzl);
    cudaGetSymbolAddress((void**)&th, g_th);   cudaGetSymbolAddress((void**)&tl, g_tl);
    cudaGetSymbolAddress((void**)&ph, g_ph);   cudaGetSymbolAddress((void**)&pl, g_pl);
    cudaGetSymbolAddress((void**)&gh, g_gh);   cudaGetSymbolAddress((void**)&gl, g_gl);
    cudaGetSymbolAddress((void**)&yh, g_yh);   cudaGetSymbolAddress((void**)&yl, g_yl);
    cudaGetSymbolAddress((void**)&Eh, g_Eh);   cudaGetSymbolAddress((void**)&El, g_El);
    cudaGetSymbolAddress((void**)&g, g_g);     cudaGetSymbolAddress((void**)&z, g_z);

    // input splits
    split_kernel<<<(B_*CIN*NS + 255)/256, 256>>>(x,  xh,  xl,  B_*CIN*NS);
    split_kernel<<<(CP*CIN + 255)/256,    256>>>(Wt, Wth, Wtl, CP*CIN);
    split_kernel<<<(CP*CIN + 255)/256,    256>>>(Wp, Wph, Wpl, CP*CIN);
    split_kernel<<<(CP*CIN + 255)/256,    256>>>(Wg, Wgh, Wgl, CP*CIN);
    split_kernel<<<(CIN*CP + 255)/256,    256>>>(Wz, Wzh, Wzl, CIN*CP);

    // projections (tensor pipe): t,p -> hi/lo bf16; g -> fp32
    hgemm3p<<<dim3(32,1,4), 512, G_SMEM>>>(Wth, Wtl, 0, xh, xl, (size_t)CIN*NS,
        nullptr, th, tl, (size_t)CP*NS, CIN, 1);
    hgemm3p<<<dim3(32,1,4), 512, G_SMEM>>>(Wph, Wpl, 0, xh, xl, (size_t)CIN*NS,
        nullptr, ph, pl, (size_t)CP*NS, CIN, 1);
    hgemm3p<<<dim3(32,1,4), 512, G_SMEM>>>(Wgh, Wgl, 0, xh, xl, (size_t)CIN*NS,
        g, nullptr, nullptr, (size_t)CP*NS, CIN, 0);

    logits_mma<<<dim3(32,4), 512, L_SMEM>>>();
    gscale_kernel<<<(B_*CP*NS)/256, 256>>>();

    // apply: y = g' @ E  (K = NS), output y hi/lo
    hgemm3p<<<dim3(32,1,4), 512, G_SMEM>>>(gh, gl, (size_t)CP*NS, Eh, El, (size_t)NS*NS,
        nullptr, yh, yl, (size_t)CP*NS, NS, 1);

    // z = Wz @ y  (M=256, K=128), fp32
    hgemm3p<<<dim3(32,2,4), 512, G_SMEM>>>(Wzh, Wzl, 0, yh, yl, (size_t)CP*NS,
        z, nullptr, nullptr, (size_t)CIN*NS, CP, 0);

    bn_reduce_kernel<<<CIN, 256>>>();
    bn_apply_kernel<<<(B_*CIN*NS)/512, 512>>>(x, gamma, beta, out);
}

// round 7
// speedup vs baseline: 2.5302x; 1.0173x over previous
#include <cuda_runtime.h>
#include <cuda_bf16.h>
#include <math.h>
#include <stdint.h>

#define B_   4
#define CIN  256
#define CP   128
#define NS   4096

__device__ float g_g[B_*CP*NS];
__device__ float g_z[B_*CIN*NS];
__device__ float g_mean[CIN];
__device__ float g_invstd[CIN];
__device__ __nv_bfloat16 g_xh[B_*CIN*NS], g_xl[B_*CIN*NS];
__device__ __nv_bfloat16 g_Wth[CP*CIN], g_Wtl[CP*CIN];
__device__ __nv_bfloat16 g_Wph[CP*CIN], g_Wpl[CP*CIN];
__device__ __nv_bfloat16 g_Wgh[CP*CIN], g_Wgl[CP*CIN];
__device__ __nv_bfloat16 g_Wzh[CIN*CP], g_Wzl[CIN*CP];
__device__ __nv_bfloat16 g_th[B_*CP*NS], g_tl[B_*CP*NS];
__device__ __nv_bfloat16 g_ph[B_*CP*NS], g_pl[B_*CP*NS];
__device__ __nv_bfloat16 g_gh[B_*CP*NS], g_gl[B_*CP*NS];
__device__ __nv_bfloat16 g_yh[B_*CP*NS], g_yl[B_*CP*NS];
__device__ __nv_bfloat16 g_Eh[(size_t)B_*NS*NS], g_El[(size_t)B_*NS*NS];

// ---------------- helpers ----------------
__device__ __forceinline__ uint32_t smem_u32(const void* p) {
    uint32_t a;
    asm("{ .reg .u64 t; cvta.to.shared.u64 t, %1; cvt.u32.u64 %0, t; }" : "=r"(a) : "l"(p));
    return a;
}
#define CP16(dst, src) asm volatile("cp.async.cg.shared.global [%0], [%1], 16;" :: "r"(dst), "l"(src))
#define CPCOMMIT() asm volatile("cp.async.commit_group;" ::: "memory")
#define CPWAIT0() asm volatile("cp.async.wait_group 0;" ::: "memory")
#define CPWAIT1() asm volatile("cp.async.wait_group 1;" ::: "memory")
#define CPWAIT2() asm volatile("cp.async.wait_group 2;" ::: "memory")

__device__ __forceinline__ void ldm_x4_t(uint32_t* r, uint32_t addr) {
    asm volatile("ldmatrix.sync.aligned.m8n8.x4.trans.shared.b16 {%0,%1,%2,%3}, [%4];"
        : "=r"(r[0]), "=r"(r[1]), "=r"(r[2]), "=r"(r[3]) : "r"(addr));
}
__device__ __forceinline__ void ldm_x4(uint32_t* r, uint32_t addr) {
    asm volatile("ldmatrix.sync.aligned.m8n8.x4.shared.b16 {%0,%1,%2,%3}, [%4];"
        : "=r"(r[0]), "=r"(r[1]), "=r"(r[2]), "=r"(r[3]) : "r"(addr));
}
__device__ __forceinline__ void ldm_x2_t(uint32_t* r, uint32_t addr) {
    asm volatile("ldmatrix.sync.aligned.m8n8.x2.trans.shared.b16 {%0,%1}, [%2];"
        : "=r"(r[0]), "=r"(r[1]) : "r"(addr));
}
__device__ __forceinline__ void mma_bf16(float* c, const uint32_t* a, const uint32_t* b) {
    asm volatile("mma.sync.aligned.m16n8k16.row.col.f32.bf16.bf16.f32 "
        "{%0,%1,%2,%3}, {%4,%5,%6,%7}, {%8,%9}, {%0,%1,%2,%3};"
        : "+f"(c[0]), "+f"(c[1]), "+f"(c[2]), "+f"(c[3])
        : "r"(a[0]), "r"(a[1]), "r"(a[2]), "r"(a[3]), "r"(b[0]), "r"(b[1]));
}
__device__ __forceinline__ void split2(float a, float b, uint32_t& h, uint32_t& l) {
    __nv_bfloat16 ha = __float2bfloat16(a), hb = __float2bfloat16(b);
    h = (uint32_t)__bfloat16_as_ushort(ha) | ((uint32_t)__bfloat16_as_ushort(hb) << 16);
    __nv_bfloat16 la = __float2bfloat16(a - __bfloat162float(ha));
    __nv_bfloat16 lb = __float2bfloat16(b - __bfloat162float(hb));
    l = (uint32_t)__bfloat16_as_ushort(la) | ((uint32_t)__bfloat16_as_ushort(lb) << 16);
}

// ============================================================
// elementwise fp32 -> bf16 hi/lo split
// ============================================================
__global__ __launch_bounds__(256) void split_kernel(
    const float* __restrict__ src, __nv_bfloat16* __restrict__ h,
    __nv_bfloat16* __restrict__ l, int n)
{
    int i = blockIdx.x*256 + threadIdx.x;
    if (i >= n) return;
    float v = src[i];
    __nv_bfloat16 hb = __float2bfloat16(v);
    h[i] = hb;
    l[i] = __float2bfloat16(v - __bfloat162float(hb));
}

// ============================================================
// shared GEMM machinery: 128x128 CTA tile, 64-k chunks, 3-stage
// ============================================================
#define ATS 72
#define ATB 18432u
#define BTS 136
#define BTB 17408u
#define ABUF (2u*ATB + 2u*BTB)
#define G_SMEM (3u*ABUF)

__device__ __forceinline__ void stage_g(uint32_t buf,
    const __nv_bfloat16* Ah, const __nv_bfloat16* Al,
    const __nv_bfloat16* Bh, const __nv_bfloat16* Bl,
    int kc, int m0, int n0, int K, int tid)
{
    #pragma unroll
    for (int i = 0; i < 2; i++) {
        int idx = tid + i*512, row = idx>>3, ch = idx&7;
        uint32_t d = (uint32_t)(row*(ATS*2) + ch*16);
        size_t so = (size_t)(m0+row)*K + kc*64 + ch*8;
        CP16(buf + d,       Ah + so);
        CP16(buf + ATB + d, Al + so);
    }
    #pragma unroll
    for (int i = 0; i < 2; i++) {
        int idx = tid + i*512, row = idx>>4, ch = idx&15;
        uint32_t d = (uint32_t)(row*(BTS*2) + ch*16);
        size_t so = (size_t)(kc*64+row)*NS + n0 + ch*8;
        CP16(buf + 2u*ATB + d,       Bh + so);
        CP16(buf + 2u*ATB + BTB + d, Bl + so);
    }
}

__device__ __forceinline__ void gemm_loop(uint32_t sb,
    const __nv_bfloat16* pAh, const __nv_bfloat16* pAl,
    const __nv_bfloat16* pBh, const __nv_bfloat16* pBl,
    int m0, int n0, int K, int nk, int tid, int wid, int lane,
    float acc[2][4][4])
{
    #pragma unroll
    for (int s = 0; s < 3; s++) {
        if (s < nk) stage_g(sb + (uint32_t)s*ABUF, pAh, pAl, pBh, pBl, s, m0, n0, K, tid);
        CPCOMMIT();
    }
    const int wc = (wid&3)*32, wn = (wid>>2)*32;
    const uint32_t rowAa = (lane&15), colAa = (lane>>4)*8;
    const uint32_t rowB = (lane&15);

    int sslot = 0;
    for (int kc = 0; kc < nk; kc++) {
        CPWAIT2();
        __syncthreads();
        const uint32_t buf = sb + (uint32_t)sslot*ABUF;
        #pragma unroll
        for (int k0 = 0; k0 < 64; k0 += 16) {
            uint32_t ah[2][4], al[2][4], bh[4][2], bl[4][2];
            #pragma unroll
            for (int ct = 0; ct < 2; ct++) {
                uint32_t ao = buf + ((wc + ct*16 + rowAa)*ATS + k0 + colAa)*2;
                ldm_x4(ah[ct], ao);
                ldm_x4(al[ct], ao + ATB);
            }
            #pragma unroll
            for (int nt = 0; nt < 4; nt++) {
                uint32_t bo = buf + 2u*ATB + ((k0+rowB)*BTS + wn + nt*8)*2;
                ldm_x2_t(bh[nt], bo);
                ldm_x2_t(bl[nt], bo + BTB);
            }
            #pragma unroll
            for (int ct = 0; ct < 2; ct++)
                #pragma unroll
                for (int nt = 0; nt < 4; nt++) {
                    mma_bf16(acc[ct][nt], ah[ct], bh[nt]);
                    mma_bf16(acc[ct][nt], ah[ct], bl[nt]);
                    mma_bf16(acc[ct][nt], al[ct], bh[nt]);
                }
        }
        __syncthreads();
        if (kc + 3 < nk)
            stage_g(buf, pAh, pAl, pBh, pBl, kc+3, m0, n0, K, tid);
        CPCOMMIT();
        sslot = (sslot == 2) ? 0 : sslot + 1;
    }
}

__device__ __forceinline__ void epi_f32(float* Cout, float acc[2][4][4],
                                        int m0, int n0, int wid, int lane)
{
    const int wc = (wid&3)*32, wn = (wid>>2)*32;
    const int r0 = lane>>2, cb = (lane&3)*2;
    #pragma unroll
    for (int ct = 0; ct < 2; ct++) {
        const int cg = m0 + wc + ct*16 + r0;
        #pragma unroll
        for (int nt = 0; nt < 4; nt++) {
            const int ng = n0 + wn + nt*8 + cb;
            *(float2*)(Cout + (size_t)cg*NS + ng)     = make_float2(acc[ct][nt][0], acc[ct][nt][1]);
            *(float2*)(Cout + (size_t)(cg+8)*NS + ng) = make_float2(acc[ct][nt][2], acc[ct][nt][3]);
        }
    }
}
__device__ __forceinline__ void epi_bf(__nv_bfloat16* ch, __nv_bfloat16* cl,
                                       float acc[2][4][4], int m0, int n0, int wid, int lane)
{
    const int wc = (wid&3)*32, wn = (wid>>2)*32;
    const int r0 = lane>>2, cb = (lane&3)*2;
    #pragma unroll
    for (int ct = 0; ct < 2; ct++) {
        const int cg = m0 + wc + ct*16 + r0;
        #pragma unroll
        for (int nt = 0; nt < 4; nt++) {
            const int ng = n0 + wn + nt*8 + cb;
            uint32_t h, l;
            split2(acc[ct][nt][0], acc[ct][nt][1], h, l);
            *(uint32_t*)(ch + (size_t)cg*NS + ng) = h;
            *(uint32_t*)(cl + (size_t)cg*NS + ng) = l;
            split2(acc[ct][nt][2], acc[ct][nt][3], h, l);
            *(uint32_t*)(ch + (size_t)(cg+8)*NS + ng) = h;
            *(uint32_t*)(cl + (size_t)(cg+8)*NS + ng) = l;
        }
    }
}

// ============================================================
// proj: one launch for t/p/g. grid (32, 3, 4), 512 thr
// ============================================================
__global__ __launch_bounds__(512) void proj_mma()
{
    extern __shared__ char smem[];
    const int b = blockIdx.z, w = blockIdx.y, n0 = blockIdx.x*128;
    const int tid = threadIdx.x, wid = tid>>5, lane = tid&31;
    const uint32_t sb = smem_u32(smem);
    const __nv_bfloat16* Ah = (w == 0) ? g_Wth : (w == 1) ? g_Wph : g_Wgh;
    const __nv_bfloat16* Al = (w == 0) ? g_Wtl : (w == 1) ? g_Wpl : g_Wgl;
    const __nv_bfloat16* Bh = g_xh + (size_t)b*CIN*NS;
    const __nv_bfloat16* Bl = g_xl + (size_t)b*CIN*NS;

    float acc[2][4][4] = {};
    gemm_loop(sb, Ah, Al, Bh, Bl, 0, n0, CIN, CIN/64, tid, wid, lane, acc);

    if (w == 0)      epi_bf(g_th + (size_t)b*CP*NS, g_tl + (size_t)b*CP*NS, acc, 0, n0, wid, lane);
    else if (w == 1) epi_bf(g_ph + (size_t)b*CP*NS, g_pl + (size_t)b*CP*NS, acc, 0, n0, wid, lane);
    else             epi_f32(g_g + (size_t)b*CP*NS, acc, 0, n0, wid, lane);
}

// ============================================================
// apply / z via generic kernel
// ============================================================
__global__ __launch_bounds__(512) void hgemm3p(
    const __nv_bfloat16* __restrict__ Ah, const __nv_bfloat16* __restrict__ Al, size_t sAb,
    const __nv_bfloat16* __restrict__ Bh, const __nv_bfloat16* __restrict__ Bl, size_t sBb,
    float* __restrict__ C, __nv_bfloat16* __restrict__ Ch, __nv_bfloat16* __restrict__ Cl,
    size_t sCb, int K, int mode)
{
    extern __shared__ char smem[];
    const int b = blockIdx.z, m0 = blockIdx.y*128, n0 = blockIdx.x*128;
    const int tid = threadIdx.x, wid = tid>>5, lane = tid&31;
    const uint32_t sb = smem_u32(smem);

    float acc[2][4][4] = {};
    gemm_loop(sb, Ah + (size_t)b*sAb, Al + (size_t)b*sAb,
              Bh + (size_t)b*sBb, Bl + (size_t)b*sBb,
              m0, n0, K, K>>6, tid, wid, lane, acc);

    if (mode == 0) epi_f32(C + (size_t)b*sCb, acc, m0, n0, wid, lane);
    else           epi_bf(Ch + (size_t)b*sCb, Cl + (size_t)b*sCb, acc, m0, n0, wid, lane);
}

// ============================================================
// logits: s = p^T t fused 3-pass; E=exp(s) hi/lo; Linv; g' scale fused
// grid (32, 4), 512 thr
// ============================================================
#define LTS 136
#define LTB 34816u
#define L_SMEM (6u*LTB)

__device__ __forceinline__ void stage_pt(uint32_t dbase, const __nv_bfloat16* sh,
                                         const __nv_bfloat16* sl, int col0, int tid) {
    #pragma unroll
    for (int i = 0; i < 4; i++) {
        int idx = tid + i*512, row = idx>>4, ch = idx&15;
        uint32_t d = (uint32_t)(row*(LTS*2) + ch*16);
        CP16(dbase + d,       sh + (size_t)row*NS + col0 + ch*8);
        CP16(dbase + LTB + d, sl + (size_t)row*NS + col0 + ch*8);
    }
}

__global__ __launch_bounds__(512) void logits_mma()
{
    extern __shared__ char smem[];
    const int b = blockIdx.y, m0 = blockIdx.x*128;
    const int tid = threadIdx.x, wid = tid>>5, lane = tid&31;
    const uint32_t sb = smem_u32(smem);
    const __nv_bfloat16* th = g_th + (size_t)b*CP*NS;
    const __nv_bfloat16* tl = g_tl + (size_t)b*CP*NS;

    stage_pt(sb, g_ph + (size_t)b*CP*NS, g_pl + (size_t)b*CP*NS, m0, tid);
    stage_pt(sb + 2u*LTB, th, tl, 0, tid);     CPCOMMIT();
    stage_pt(sb + 4u*LTB, th, tl, 128, tid);   CPCOMMIT();

    const int mw = (wid&3)*32, nw = (wid>>2)*32;
    const uint32_t rowA = (lane&7) + ((lane>>4)<<3);
    const uint32_t colA = ((lane>>3)&1)*8;
    const uint32_t rowB = (lane&15);
    const int r0 = lane>>2, cb = (lane&3)*2;

    float acc[2][4][4] = {};
    float rs[2][2] = {};

    for (int nc = 0; nc < 32; nc++) {
        if (nc >= 30) { CPWAIT0(); } else { CPWAIT1(); }
        __syncthreads();
        const uint32_t bufB = sb + 2u*LTB + (uint32_t)(nc&1)*(2u*LTB);
        #pragma unroll
        for (int k0 = 0; k0 < 128; k0 += 16) {
            uint32_t ah[2][4], al[2][4], bh[4][2], bl[4][2];
            #pragma unroll
            for (int mt = 0; mt < 2; mt++) {
                uint32_t ao = sb + ((k0+rowA)*LTS + mw + mt*16 + colA)*2;
                ldm_x4_t(ah[mt], ao);
                ldm_x4_t(al[mt], ao + LTB);
            }
            #pragma unroll
            for (int nt = 0; nt < 4; nt++) {
                uint32_t bo = bufB + ((k0+rowB)*LTS + nw + nt*8)*2;
                ldm_x2_t(bh[nt], bo);
                ldm_x2_t(bl[nt], bo + LTB);
            }
            #pragma unroll
            for (int mt = 0; mt < 2; mt++)
                #pragma unroll
                for (int nt = 0; nt < 4; nt++) {
                    mma_bf16(acc[mt][nt], ah[mt], bh[nt]);
                    mma_bf16(acc[mt][nt], ah[mt], bl[nt]);
                    mma_bf16(acc[mt][nt], al[mt], bh[nt]);
                }
        }
        __syncthreads();
        if (nc + 2 < 32) {
            stage_pt(sb + 2u*LTB + (uint32_t)(nc&1)*(2u*LTB), th, tl, (nc+2)*128, tid);
            CPCOMMIT();
        }
        #pragma unroll
        for (int mt = 0; mt < 2; mt++) {
            const int mg = m0 + mw + mt*16 + r0;
            #pragma unroll
            for (int nt = 0; nt < 4; nt++) {
                float e0 = __expf(acc[mt][nt][0]);
                float e1 = __expf(acc[mt][nt][1]);
                float e2 = __expf(acc[mt][nt][2]);
                float e3 = __expf(acc[mt][nt][3]);
                rs[mt][0] += e0 + e1;
                rs[mt][1] += e2 + e3;
                const int ng = nc*128 + nw + nt*8 + cb;
                uint32_t h, l;
                size_t o = ((size_t)b*NS + mg)*NS + ng;
                split2(e0, e1, h, l);
                *(uint32_t*)(g_Eh + o) = h; *(uint32_t*)(g_El + o) = l;
                o += (size_t)8*NS;
                split2(e2, e3, h, l);
                *(uint32_t*)(g_Eh + o) = h; *(uint32_t*)(g_El + o) = l;
                acc[mt][nt][0]=acc[mt][nt][1]=acc[mt][nt][2]=acc[mt][nt][3]=0.f;
            }
        }
    }

    // rowsum -> Linv in smem
    #pragma unroll
    for (int mt = 0; mt < 2; mt++)
        #pragma unroll
        for (int h = 0; h < 2; h++) {
            rs[mt][h] += __shfl_xor_sync(0xFFFFFFFF, rs[mt][h], 1);
            rs[mt][h] += __shfl_xor_sync(0xFFFFFFFF, rs[mt][h], 2);
        }
    __syncthreads();
    float* red = (float*)smem;
    if ((lane&3) == 0) {
        #pragma unroll
        for (int mt = 0; mt < 2; mt++)
            #pragma unroll
            for (int h = 0; h < 2; h++)
                red[(wid>>2)*128 + mw + mt*16 + r0 + h*8] = rs[mt][h];
    }
    __syncthreads();
    float* linv = (float*)(smem + 2048);
    if (tid < 128)
        linv[tid] = 1.0f / (red[tid] + red[128+tid] + red[256+tid] + red[384+tid]);
    __syncthreads();

    // fused gscale: g'[c, m0..m0+128) = g * Linv -> bf16 hi/lo
    {
        const int c = tid >> 2, ms = (tid & 3) * 32;
        const float* gp = g_g + ((size_t)b*CP + c)*NS + m0 + ms;
        __nv_bfloat16* ghp = g_gh + ((size_t)b*CP + c)*NS + m0 + ms;
        __nv_bfloat16* glp = g_gl + ((size_t)b*CP + c)*NS + m0 + ms;
        #pragma unroll
        for (int j = 0; j < 32; j += 4) {
            float4 v = *(const float4*)(gp + j);
            v.x *= linv[ms+j]; v.y *= linv[ms+j+1]; v.z *= linv[ms+j+2]; v.w *= linv[ms+j+3];
            uint32_t h0, l0, h1, l1;
            split2(v.x, v.y, h0, l0);
            split2(v.z, v.w, h1, l1);
            *(uint2*)(ghp + j) = make_uint2(h0, h1);
            *(uint2*)(glp + j) = make_uint2(l0, l1);
        }
    }
}

// ============================================================
// BatchNorm
// ============================================================
__global__ __launch_bounds__(256) void bn_reduce_kernel()
{
    const int c = blockIdx.x, tid = threadIdx.x;
    float s = 0.f, s2 = 0.f;
    for (int b = 0; b < B_; b++) {
        const float* zp = g_z + ((size_t)b*CIN + c)*NS;
        for (int i = tid; i < NS; i += 256) { float v = zp[i]; s += v; s2 += v*v; }
    }
    __shared__ float r1[256], r2[256];
    r1[tid] = s; r2[tid] = s2; __syncthreads();
    #pragma unroll
    for (int st = 128; st > 0; st >>= 1) {
        if (tid < st) { r1[tid] += r1[tid+st]; r2[tid] += r2[tid+st]; }
        __syncthreads();
    }
    if (tid == 0) {
        const float inv_n = 1.0f / (float)(B_*NS);
        float mean = r1[0]*inv_n, var = r2[0]*inv_n - mean*mean;
        g_mean[c] = mean;
        g_invstd[c] = rsqrtf(var + 1e-5f);
    }
}

__global__ __launch_bounds__(512) void bn_apply_kernel(
    const float* __restrict__ x, const float* __restrict__ gamma,
    const float* __restrict__ beta, float* __restrict__ out)
{
    size_t idx = (size_t)blockIdx.x*512 + threadIdx.x;
    int c = (int)((idx / NS) % CIN);
    out[idx] = (g_z[idx] - g_mean[c])*g_invstd[c]*gamma[c] + beta[c] + x[idx];
}

// ============================================================
extern "C" void kernel_launch(void* const* d_in, const int* in_sizes, int n_in,
                              void* d_out, int out_size)
{
    const float* x     = (const float*)d_in[0];
    const float* Wt    = (const float*)d_in[1];
    const float* Wp    = (const float*)d_in[2];
    const float* Wg    = (const float*)d_in[3];
    const float* Wz    = (const float*)d_in[4];
    const float* gamma = (const float*)d_in[5];
    const float* beta  = (const float*)d_in[6];
    float* out = (float*)d_out;

    cudaFuncSetAttribute(hgemm3p,    cudaFuncAttributeMaxDynamicSharedMemorySize, G_SMEM);
    cudaFuncSetAttribute(proj_mma,   cudaFuncAttributeMaxDynamicSharedMemorySize, G_SMEM);
    cudaFuncSetAttribute(logits_mma, cudaFuncAttributeMaxDynamicSharedMemorySize, L_SMEM);

    __nv_bfloat16 *xh, *xl, *Wth, *Wtl, *Wph, *Wpl, *Wgh, *Wgl, *Wzh, *Wzl;
    __nv_bfloat16 *gh, *gl, *yh, *yl, *Eh, *El;
    float *z;
    cudaGetSymbolAddress((void**)&xh, g_xh);   cudaGetSymbolAddress((void**)&xl, g_xl);
    cudaGetSymbolAddress((void**)&Wth, g_Wth); cudaGetSymbolAddress((void**)&Wtl, g_Wtl);
    cudaGetSymbolAddress((void**)&Wph, g_Wph); cudaGetSymbolAddress((void**)&Wpl, g_Wpl);
    cudaGetSymbolAddress((void**)&Wgh, g_Wgh); cudaGetSymbolAddress((void**)&Wgl, g_Wgl);
    cudaGetSymbolAddress((void**)&Wzh, g_Wzh); cudaGetSymbolAddress((void**)&Wzl, g_Wzl);
    cudaGetSymbolAddress((void**)&gh, g_gh);   cudaGetSymbolAddress((void**)&gl, g_gl);
    cudaGetSymbolAddress((void**)&yh, g_yh);   cudaGetSymbolAddress((void**)&yl, g_yl);
    cudaGetSymbolAddress((void**)&Eh, g_Eh);   cudaGetSymbolAddress((void**)&El, g_El);
    cudaGetSymbolAddress((void**)&z, g_z);

    split_kernel<<<(B_*CIN*NS + 255)/256, 256>>>(x,  xh,  xl,  B_*CIN*NS);
    split_kernel<<<(CP*CIN + 255)/256,    256>>>(Wt, Wth, Wtl, CP*CIN);
    split_kernel<<<(CP*CIN + 255)/256,    256>>>(Wp, Wph, Wpl, CP*CIN);
    split_kernel<<<(CP*CIN + 255)/256,    256>>>(Wg, Wgh, Wgl, CP*CIN);
    split_kernel<<<(CIN*CP + 255)/256,    256>>>(Wz, Wzh, Wzl, CIN*CP);

    proj_mma<<<dim3(32,3,4), 512, G_SMEM>>>();
    logits_mma<<<dim3(32,4), 512, L_SMEM>>>();

    hgemm3p<<<dim3(32,1,4), 512, G_SMEM>>>(gh, gl, (size_t)CP*NS, Eh, El, (size_t)NS*NS,
        nullptr, yh, yl, (size_t)CP*NS, NS, 1);
    hgemm3p<<<dim3(32,2,4), 512, G_SMEM>>>(Wzh, Wzl, 0, yh, yl, (size_t)CP*NS,
        z, nullptr, nullptr, (size_t)CIN*NS, CP, 0);

    bn_reduce_kernel<<<CIN, 256>>>();
    bn_apply_kernel<<<(B_*CIN*NS)/512, 512>>>(x, gamma, beta, out);
}

// round 8
// speedup vs baseline: 2.5326x; 1.0009x over previous
#include <cuda_runtime.h>
#include <cuda_bf16.h>
#include <math.h>
#include <stdint.h>

#define B_   4
#define CIN  256
#define CP   128
#define NS   4096

__device__ float g_g[B_*CP*NS];
__device__ float g_z[B_*CIN*NS];
__device__ float g_mean[CIN];
__device__ float g_invstd[CIN];
__device__ __nv_bfloat16 g_xh[B_*CIN*NS], g_xl[B_*CIN*NS];
__device__ __nv_bfloat16 g_Wth[CP*CIN], g_Wtl[CP*CIN];
__device__ __nv_bfloat16 g_Wph[CP*CIN], g_Wpl[CP*CIN];
__device__ __nv_bfloat16 g_Wgh[CP*CIN], g_Wgl[CP*CIN];
__device__ __nv_bfloat16 g_Wzh[CIN*CP], g_Wzl[CIN*CP];
__device__ __nv_bfloat16 g_th[B_*CP*NS], g_tl[B_*CP*NS];
__device__ __nv_bfloat16 g_ph[B_*CP*NS], g_pl[B_*CP*NS];
__device__ __nv_bfloat16 g_gh[B_*CP*NS], g_gl[B_*CP*NS];
__device__ __nv_bfloat16 g_yh[B_*CP*NS], g_yl[B_*CP*NS];
__device__ __nv_bfloat16 g_Eh[(size_t)B_*NS*NS], g_El[(size_t)B_*NS*NS];

// ---------------- helpers ----------------
__device__ __forceinline__ uint32_t smem_u32(const void* p) {
    uint32_t a;
    asm("{ .reg .u64 t; cvta.to.shared.u64 t, %1; cvt.u32.u64 %0, t; }" : "=r"(a) : "l"(p));
    return a;
}
#define CP16(dst, src) asm volatile("cp.async.cg.shared.global [%0], [%1], 16;" :: "r"(dst), "l"(src))
#define CPCOMMIT() asm volatile("cp.async.commit_group;" ::: "memory")
#define CPWAIT0() asm volatile("cp.async.wait_group 0;" ::: "memory")
#define CPWAIT1() asm volatile("cp.async.wait_group 1;" ::: "memory")
#define CPWAIT2() asm volatile("cp.async.wait_group 2;" ::: "memory")

__device__ __forceinline__ void ldm_x4_t(uint32_t* r, uint32_t addr) {
    asm volatile("ldmatrix.sync.aligned.m8n8.x4.trans.shared.b16 {%0,%1,%2,%3}, [%4];"
        : "=r"(r[0]), "=r"(r[1]), "=r"(r[2]), "=r"(r[3]) : "r"(addr));
}
__device__ __forceinline__ void ldm_x4(uint32_t* r, uint32_t addr) {
    asm volatile("ldmatrix.sync.aligned.m8n8.x4.shared.b16 {%0,%1,%2,%3}, [%4];"
        : "=r"(r[0]), "=r"(r[1]), "=r"(r[2]), "=r"(r[3]) : "r"(addr));
}
__device__ __forceinline__ void mma_bf16(float* c, const uint32_t* a, const uint32_t* b) {
    asm volatile("mma.sync.aligned.m16n8k16.row.col.f32.bf16.bf16.f32 "
        "{%0,%1,%2,%3}, {%4,%5,%6,%7}, {%8,%9}, {%0,%1,%2,%3};"
        : "+f"(c[0]), "+f"(c[1]), "+f"(c[2]), "+f"(c[3])
        : "r"(a[0]), "r"(a[1]), "r"(a[2]), "r"(a[3]), "r"(b[0]), "r"(b[1]));
}
__device__ __forceinline__ void split2(float a, float b, uint32_t& h, uint32_t& l) {
    __nv_bfloat16 ha = __float2bfloat16(a), hb = __float2bfloat16(b);
    h = (uint32_t)__bfloat16_as_ushort(ha) | ((uint32_t)__bfloat16_as_ushort(hb) << 16);
    __nv_bfloat16 la = __float2bfloat16(a - __bfloat162float(ha));
    __nv_bfloat16 lb = __float2bfloat16(b - __bfloat162float(hb));
    l = (uint32_t)__bfloat16_as_ushort(la) | ((uint32_t)__bfloat16_as_ushort(lb) << 16);
}

// ============================================================
// elementwise fp32 -> bf16 hi/lo split
// ============================================================
__global__ __launch_bounds__(256) void split_kernel(
    const float* __restrict__ src, __nv_bfloat16* __restrict__ h,
    __nv_bfloat16* __restrict__ l, int n)
{
    int i = blockIdx.x*256 + threadIdx.x;
    if (i >= n) return;
    float v = src[i];
    __nv_bfloat16 hb = __float2bfloat16(v);
    h[i] = hb;
    l[i] = __float2bfloat16(v - __bfloat162float(hb));
}

// ============================================================
// shared GEMM machinery: 128x128 CTA tile, 64-k chunks, 3-stage
// ============================================================
#define ATS 72
#define ATB 18432u
#define BTS 136
#define BTB 17408u
#define ABUF (2u*ATB + 2u*BTB)
#define G_SMEM (3u*ABUF)

__device__ __forceinline__ void stage_g(uint32_t buf,
    const __nv_bfloat16* Ah, const __nv_bfloat16* Al,
    const __nv_bfloat16* Bh, const __nv_bfloat16* Bl,
    int kc, int m0, int n0, int K, int tid)
{
    #pragma unroll
    for (int i = 0; i < 2; i++) {
        int idx = tid + i*512, row = idx>>3, ch = idx&7;
        uint32_t d = (uint32_t)(row*(ATS*2) + ch*16);
        size_t so = (size_t)(m0+row)*K + kc*64 + ch*8;
        CP16(buf + d,       Ah + so);
        CP16(buf + ATB + d, Al + so);
    }
    #pragma unroll
    for (int i = 0; i < 2; i++) {
        int idx = tid + i*512, row = idx>>4, ch = idx&15;
        uint32_t d = (uint32_t)(row*(BTS*2) + ch*16);
        size_t so = (size_t)(kc*64+row)*NS + n0 + ch*8;
        CP16(buf + 2u*ATB + d,       Bh + so);
        CP16(buf + 2u*ATB + BTB + d, Bl + so);
    }
}

__device__ __forceinline__ void gemm_loop(uint32_t sb,
    const __nv_bfloat16* pAh, const __nv_bfloat16* pAl,
    const __nv_bfloat16* pBh, const __nv_bfloat16* pBl,
    int m0, int n0, int K, int nk, int tid, int wid, int lane,
    float acc[2][4][4])
{
    #pragma unroll
    for (int s = 0; s < 3; s++) {
        if (s < nk) stage_g(sb + (uint32_t)s*ABUF, pAh, pAl, pBh, pBl, s, m0, n0, K, tid);
        CPCOMMIT();
    }
    const int wc = (wid&3)*32, wn = (wid>>2)*32;
    const uint32_t rowAa = (lane&15), colAa = (lane>>4)*8;
    const uint32_t rowB16 = (lane&15), colB8 = (lane>>4)*8;

    int sslot = 0;
    for (int kc = 0; kc < nk; kc++) {
        CPWAIT2();
        __syncthreads();
        const uint32_t buf = sb + (uint32_t)sslot*ABUF;
        #pragma unroll
        for (int k0 = 0; k0 < 64; k0 += 16) {
            uint32_t ah[2][4], al[2][4], bh[2][4], bl[2][4];
            #pragma unroll
            for (int ct = 0; ct < 2; ct++) {
                uint32_t ao = buf + ((wc + ct*16 + rowAa)*ATS + k0 + colAa)*2;
                ldm_x4(ah[ct], ao);
                ldm_x4(al[ct], ao + ATB);
            }
            #pragma unroll
            for (int j = 0; j < 2; j++) {
                uint32_t bo = buf + 2u*ATB + ((k0+rowB16)*BTS + wn + j*16 + colB8)*2;
                ldm_x4_t(bh[j], bo);
                ldm_x4_t(bl[j], bo + BTB);
            }
            // pass-major: acc reuse distance = 8 MMAs
            #pragma unroll
            for (int ct = 0; ct < 2; ct++)
                #pragma unroll
                for (int nt = 0; nt < 4; nt++)
                    mma_bf16(acc[ct][nt], ah[ct], &bh[nt>>1][(nt&1)*2]);
            #pragma unroll
            for (int ct = 0; ct < 2; ct++)
                #pragma unroll
                for (int nt = 0; nt < 4; nt++)
                    mma_bf16(acc[ct][nt], ah[ct], &bl[nt>>1][(nt&1)*2]);
            #pragma unroll
            for (int ct = 0; ct < 2; ct++)
                #pragma unroll
                for (int nt = 0; nt < 4; nt++)
                    mma_bf16(acc[ct][nt], al[ct], &bh[nt>>1][(nt&1)*2]);
        }
        __syncthreads();
        if (kc + 3 < nk)
            stage_g(buf, pAh, pAl, pBh, pBl, kc+3, m0, n0, K, tid);
        CPCOMMIT();
        sslot = (sslot == 2) ? 0 : sslot + 1;
    }
}

__device__ __forceinline__ void epi_f32(float* Cout, float acc[2][4][4],
                                        int m0, int n0, int wid, int lane)
{
    const int wc = (wid&3)*32, wn = (wid>>2)*32;
    const int r0 = lane>>2, cb = (lane&3)*2;
    #pragma unroll
    for (int ct = 0; ct < 2; ct++) {
        const int cg = m0 + wc + ct*16 + r0;
        #pragma unroll
        for (int nt = 0; nt < 4; nt++) {
            const int ng = n0 + wn + nt*8 + cb;
            *(float2*)(Cout + (size_t)cg*NS + ng)     = make_float2(acc[ct][nt][0], acc[ct][nt][1]);
            *(float2*)(Cout + (size_t)(cg+8)*NS + ng) = make_float2(acc[ct][nt][2], acc[ct][nt][3]);
        }
    }
}
__device__ __forceinline__ void epi_bf(__nv_bfloat16* ch, __nv_bfloat16* cl,
                                       float acc[2][4][4], int m0, int n0, int wid, int lane)
{
    const int wc = (wid&3)*32, wn = (wid>>2)*32;
    const int r0 = lane>>2, cb = (lane&3)*2;
    #pragma unroll
    for (int ct = 0; ct < 2; ct++) {
        const int cg = m0 + wc + ct*16 + r0;
        #pragma unroll
        for (int nt = 0; nt < 4; nt++) {
            const int ng = n0 + wn + nt*8 + cb;
            uint32_t h, l;
            split2(acc[ct][nt][0], acc[ct][nt][1], h, l);
            *(uint32_t*)(ch + (size_t)cg*NS + ng) = h;
            *(uint32_t*)(cl + (size_t)cg*NS + ng) = l;
            split2(acc[ct][nt][2], acc[ct][nt][3], h, l);
            *(uint32_t*)(ch + (size_t)(cg+8)*NS + ng) = h;
            *(uint32_t*)(cl + (size_t)(cg+8)*NS + ng) = l;
        }
    }
}

// ============================================================
// proj: one launch for t/p/g. grid (32, 3, 4), 512 thr
// ============================================================
__global__ __launch_bounds__(512) void proj_mma()
{
    extern __shared__ char smem[];
    const int b = blockIdx.z, w = blockIdx.y, n0 = blockIdx.x*128;
    const int tid = threadIdx.x, wid = tid>>5, lane = tid&31;
    const uint32_t sb = smem_u32(smem);
    const __nv_bfloat16* Ah = (w == 0) ? g_Wth : (w == 1) ? g_Wph : g_Wgh;
    const __nv_bfloat16* Al = (w == 0) ? g_Wtl : (w == 1) ? g_Wpl : g_Wgl;
    const __nv_bfloat16* Bh = g_xh + (size_t)b*CIN*NS;
    const __nv_bfloat16* Bl = g_xl + (size_t)b*CIN*NS;

    float acc[2][4][4] = {};
    gemm_loop(sb, Ah, Al, Bh, Bl, 0, n0, CIN, CIN/64, tid, wid, lane, acc);

    if (w == 0)      epi_bf(g_th + (size_t)b*CP*NS, g_tl + (size_t)b*CP*NS, acc, 0, n0, wid, lane);
    else if (w == 1) epi_bf(g_ph + (size_t)b*CP*NS, g_pl + (size_t)b*CP*NS, acc, 0, n0, wid, lane);
    else             epi_f32(g_g + (size_t)b*CP*NS, acc, 0, n0, wid, lane);
}

// ============================================================
// apply / z via generic kernel
// ============================================================
__global__ __launch_bounds__(512) void hgemm3p(
    const __nv_bfloat16* __restrict__ Ah, const __nv_bfloat16* __restrict__ Al, size_t sAb,
    const __nv_bfloat16* __restrict__ Bh, const __nv_bfloat16* __restrict__ Bl, size_t sBb,
    float* __restrict__ C, __nv_bfloat16* __restrict__ Ch, __nv_bfloat16* __restrict__ Cl,
    size_t sCb, int K, int mode)
{
    extern __shared__ char smem[];
    const int b = blockIdx.z, m0 = blockIdx.y*128, n0 = blockIdx.x*128;
    const int tid = threadIdx.x, wid = tid>>5, lane = tid&31;
    const uint32_t sb = smem_u32(smem);

    float acc[2][4][4] = {};
    gemm_loop(sb, Ah + (size_t)b*sAb, Al + (size_t)b*sAb,
              Bh + (size_t)b*sBb, Bl + (size_t)b*sBb,
              m0, n0, K, K>>6, tid, wid, lane, acc);

    if (mode == 0) epi_f32(C + (size_t)b*sCb, acc, m0, n0, wid, lane);
    else           epi_bf(Ch + (size_t)b*sCb, Cl + (size_t)b*sCb, acc, m0, n0, wid, lane);
}

// ============================================================
// logits: s = p^T t fused 3-pass; E=exp(s) hi/lo; Linv; gscale fused
// grid (32, 4), 512 thr
// ============================================================
#define LTS 136
#define LTB 34816u
#define L_SMEM (6u*LTB)

__device__ __forceinline__ void stage_pt(uint32_t dbase, const __nv_bfloat16* sh,
                                         const __nv_bfloat16* sl, int col0, int tid) {
    #pragma unroll
    for (int i = 0; i < 4; i++) {
        int idx = tid + i*512, row = idx>>4, ch = idx&15;
        uint32_t d = (uint32_t)(row*(LTS*2) + ch*16);
        CP16(dbase + d,       sh + (size_t)row*NS + col0 + ch*8);
        CP16(dbase + LTB + d, sl + (size_t)row*NS + col0 + ch*8);
    }
}

__global__ __launch_bounds__(512) void logits_mma()
{
    extern __shared__ char smem[];
    const int b = blockIdx.y, m0 = blockIdx.x*128;
    const int tid = threadIdx.x, wid = tid>>5, lane = tid&31;
    const uint32_t sb = smem_u32(smem);
    const __nv_bfloat16* th = g_th + (size_t)b*CP*NS;
    const __nv_bfloat16* tl = g_tl + (size_t)b*CP*NS;

    stage_pt(sb, g_ph + (size_t)b*CP*NS, g_pl + (size_t)b*CP*NS, m0, tid);
    stage_pt(sb + 2u*LTB, th, tl, 0, tid);     CPCOMMIT();
    stage_pt(sb + 4u*LTB, th, tl, 128, tid);   CPCOMMIT();

    const int mw = (wid&3)*32, nw = (wid>>2)*32;
    const uint32_t rowA = (lane&7) + ((lane>>4)<<3);
    const uint32_t colA = ((lane>>3)&1)*8;
    const uint32_t rowB16 = (lane&15), colB8 = (lane>>4)*8;
    const int r0 = lane>>2, cb = (lane&3)*2;

    float acc[2][4][4] = {};
    float rs[2][2] = {};

    for (int nc = 0; nc < 32; nc++) {
        if (nc >= 30) { CPWAIT0(); } else { CPWAIT1(); }
        __syncthreads();
        const uint32_t bufB = sb + 2u*LTB + (uint32_t)(nc&1)*(2u*LTB);
        #pragma unroll
        for (int k0 = 0; k0 < 128; k0 += 16) {
            uint32_t ah[2][4], al[2][4], bh[2][4], bl[2][4];
            #pragma unroll
            for (int mt = 0; mt < 2; mt++) {
                uint32_t ao = sb + ((k0+rowA)*LTS + mw + mt*16 + colA)*2;
                ldm_x4_t(ah[mt], ao);
                ldm_x4_t(al[mt], ao + LTB);
            }
            #pragma unroll
            for (int j = 0; j < 2; j++) {
                uint32_t bo = bufB + ((k0+rowB16)*LTS + nw + j*16 + colB8)*2;
                ldm_x4_t(bh[j], bo);
                ldm_x4_t(bl[j], bo + LTB);
            }
            #pragma unroll
            for (int mt = 0; mt < 2; mt++)
                #pragma unroll
                for (int nt = 0; nt < 4; nt++)
                    mma_bf16(acc[mt][nt], ah[mt], &bh[nt>>1][(nt&1)*2]);
            #pragma unroll
            for (int mt = 0; mt < 2; mt++)
                #pragma unroll
                for (int nt = 0; nt < 4; nt++)
                    mma_bf16(acc[mt][nt], ah[mt], &bl[nt>>1][(nt&1)*2]);
            #pragma unroll
            for (int mt = 0; mt < 2; mt++)
                #pragma unroll
                for (int nt = 0; nt < 4; nt++)
                    mma_bf16(acc[mt][nt], al[mt], &bh[nt>>1][(nt&1)*2]);
        }
        __syncthreads();
        if (nc + 2 < 32) {
            stage_pt(sb + 2u*LTB + (uint32_t)(nc&1)*(2u*LTB), th, tl, (nc+2)*128, tid);
            CPCOMMIT();
        }
        #pragma unroll
        for (int mt = 0; mt < 2; mt++) {
            const int mg = m0 + mw + mt*16 + r0;
            #pragma unroll
            for (int nt = 0; nt < 4; nt++) {
                float e0 = __expf(acc[mt][nt][0]);
                float e1 = __expf(acc[mt][nt][1]);
                float e2 = __expf(acc[mt][nt][2]);
                float e3 = __expf(acc[mt][nt][3]);
                rs[mt][0] += e0 + e1;
                rs[mt][1] += e2 + e3;
                const int ng = nc*128 + nw + nt*8 + cb;
                uint32_t h, l;
                size_t o = ((size_t)b*NS + mg)*NS + ng;
                split2(e0, e1, h, l);
                *(uint32_t*)(g_Eh + o) = h; *(uint32_t*)(g_El + o) = l;
                o += (size_t)8*NS;
                split2(e2, e3, h, l);
                *(uint32_t*)(g_Eh + o) = h; *(uint32_t*)(g_El + o) = l;
                acc[mt][nt][0]=acc[mt][nt][1]=acc[mt][nt][2]=acc[mt][nt][3]=0.f;
            }
        }
    }

    #pragma unroll
    for (int mt = 0; mt < 2; mt++)
        #pragma unroll
        for (int h = 0; h < 2; h++) {
            rs[mt][h] += __shfl_xor_sync(0xFFFFFFFF, rs[mt][h], 1);
            rs[mt][h] += __shfl_xor_sync(0xFFFFFFFF, rs[mt][h], 2);
        }
    __syncthreads();
    float* red = (float*)smem;
    if ((lane&3) == 0) {
        #pragma unroll
        for (int mt = 0; mt < 2; mt++)
            #pragma unroll
            for (int h = 0; h < 2; h++)
                red[(wid>>2)*128 + mw + mt*16 + r0 + h*8] = rs[mt][h];
    }
    __syncthreads();
    float* linv = (float*)(smem + 2048);
    if (tid < 128)
        linv[tid] = 1.0f / (red[tid] + red[128+tid] + red[256+tid] + red[384+tid]);
    __syncthreads();

    // fused gscale: g'[c, m0..m0+128) = g * Linv -> bf16 hi/lo
    {
        const int c = tid >> 2, ms = (tid & 3) * 32;
        const float* gp = g_g + ((size_t)b*CP + c)*NS + m0 + ms;
        __nv_bfloat16* ghp = g_gh + ((size_t)b*CP + c)*NS + m0 + ms;
        __nv_bfloat16* glp = g_gl + ((size_t)b*CP + c)*NS + m0 + ms;
        #pragma unroll
        for (int j = 0; j < 32; j += 4) {
            float4 v = *(const float4*)(gp + j);
            v.x *= linv[ms+j]; v.y *= linv[ms+j+1]; v.z *= linv[ms+j+2]; v.w *= linv[ms+j+3];
            uint32_t h0, l0, h1, l1;
            split2(v.x, v.y, h0, l0);
            split2(v.z, v.w, h1, l1);
            *(uint2*)(ghp + j) = make_uint2(h0, h1);
            *(uint2*)(glp + j) = make_uint2(l0, l1);
        }
    }
}

// ============================================================
// BatchNorm
// ============================================================
__global__ __launch_bounds__(256) void bn_reduce_kernel()
{
    const int c = blockIdx.x, tid = threadIdx.x;
    float s = 0.f, s2 = 0.f;
    for (int b = 0; b < B_; b++) {
        const float* zp = g_z + ((size_t)b*CIN + c)*NS;
        for (int i = tid; i < NS; i += 256) { float v = zp[i]; s += v; s2 += v*v; }
    }
    __shared__ float r1[256], r2[256];
    r1[tid] = s; r2[tid] = s2; __syncthreads();
    #pragma unroll
    for (int st = 128; st > 0; st >>= 1) {
        if (tid < st) { r1[tid] += r1[tid+st]; r2[tid] += r2[tid+st]; }
        __syncthreads();
    }
    if (tid == 0) {
        const float inv_n = 1.0f / (float)(B_*NS);
        float mean = r1[0]*inv_n, var = r2[0]*inv_n - mean*mean;
        g_mean[c] = mean;
        g_invstd[c] = rsqrtf(var + 1e-5f);
    }
}

__global__ __launch_bounds__(512) void bn_apply_kernel(
    const float* __restrict__ x, const float* __restrict__ gamma,
    const float* __restrict__ beta, float* __restrict__ out)
{
    size_t idx = (size_t)blockIdx.x*512 + threadIdx.x;
    int c = (int)((idx / NS) % CIN);
    out[idx] = (g_z[idx] - g_mean[c])*g_invstd[c]*gamma[c] + beta[c] + x[idx];
}

// ============================================================
extern "C" void kernel_launch(void* const* d_in, const int* in_sizes, int n_in,
                              void* d_out, int out_size)
{
    const float* x     = (const float*)d_in[0];
    const float* Wt    = (const float*)d_in[1];
    const float* Wp    = (const float*)d_in[2];
    const float* Wg    = (const float*)d_in[3];
    const float* Wz    = (const float*)d_in[4];
    const float* gamma = (const float*)d_in[5];
    const float* beta  = (const float*)d_in[6];
    float* out = (float*)d_out;

    cudaFuncSetAttribute(hgemm3p,    cudaFuncAttributeMaxDynamicSharedMemorySize, G_SMEM);
    cudaFuncSetAttribute(proj_mma,   cudaFuncAttributeMaxDynamicSharedMemorySize, G_SMEM);
    cudaFuncSetAttribute(logits_mma, cudaFuncAttributeMaxDynamicSharedMemorySize, L_SMEM);

    __nv_bfloat16 *xh, *xl, *Wth, *Wtl, *Wph, *Wpl, *Wgh, *Wgl, *Wzh, *Wzl;
    __nv_bfloat16 *gh, *gl, *yh, *yl, *Eh, *El;
    float *z;
    cudaGetSymbolAddress((void**)&xh, g_xh);   cudaGetSymbolAddress((void**)&xl, g_xl);
    cudaGetSymbolAddress((void**)&Wth, g_Wth); cudaGetSymbolAddress((void**)&Wtl, g_Wtl);
    cudaGetSymbolAddress((void**)&Wph, g_Wph); cudaGetSymbolAddress((void**)&Wpl, g_Wpl);
    cudaGetSymbolAddress((void**)&Wgh, g_Wgh); cudaGetSymbolAddress((void**)&Wgl, g_Wgl);
    cudaGetSymbolAddress((void**)&Wzh, g_Wzh); cudaGetSymbolAddress((void**)&Wzl, g_Wzl);
    cudaGetSymbolAddress((void**)&gh, g_gh);   cudaGetSymbolAddress((void**)&gl, g_gl);
    cudaGetSymbolAddress((void**)&yh, g_yh);   cudaGetSymbolAddress((void**)&yl, g_yl);
    cudaGetSymbolAddress((void**)&Eh, g_Eh);   cudaGetSymbolAddress((void**)&El, g_El);
    cudaGetSymbolAddress((void**)&z, g_z);

    split_kernel<<<(B_*CIN*NS + 255)/256, 256>>>(x,  xh,  xl,  B_*CIN*NS);
    split_kernel<<<(CP*CIN + 255)/256,    256>>>(Wt, Wth, Wtl, CP*CIN);
    split_kernel<<<(CP*CIN + 255)/256,    256>>>(Wp, Wph, Wpl, CP*CIN);
    split_kernel<<<(CP*CIN + 255)/256,    256>>>(Wg, Wgh, Wgl, CP*CIN);
    split_kernel<<<(CIN*CP + 255)/256,    256>>>(Wz, Wzh, Wzl, CIN*CP);

    proj_mma<<<dim3(32,3,4), 512, G_SMEM>>>();
    logits_mma<<<dim3(32,4), 512, L_SMEM>>>();

    hgemm3p<<<dim3(32,1,4), 512, G_SMEM>>>(gh, gl, (size_t)CP*NS, Eh, El, (size_t)NS*NS,
        nullptr, yh, yl, (size_t)CP*NS, NS, 1);
    hgemm3p<<<dim3(32,2,4), 512, G_SMEM>>>(Wzh, Wzl, 0, yh, yl, (size_t)CP*NS,
        z, nullptr, nullptr, (size_t)CIN*NS, CP, 0);

    bn_reduce_kernel<<<CIN, 256>>>();
    bn_apply_kernel<<<(B_*CIN*NS)/512, 512>>>(x, gamma, beta, out);
}